// round 4
// baseline (speedup 1.0000x reference)
#include <cuda_runtime.h>
#include <cuda_bf16.h>
#include <cstdint>
#include <math.h>

#define EMBD 512
#define NHEADS 8
#define HDIM 64
#define NDEPTH 6
#define NCONT 100
#define NCAT 28
#define NHID 682
#define BSZ 128
#define SEQ 129
#define NTOK (BSZ*SEQ)      /* 16512 */
#define QKVN (3*EMBD)       /* 1536  */
#define HID2 (2*NHID)       /* 1364  */
#define NBH (BSZ*NHEADS)    /* 1024  */

#define KPAD_E 512
#define KPAD_H 704
#define W0_NPAD 1536

// ---------------- scratch (device globals) ---------------------------------
__device__ float g_h[NTOK*EMBD];
__device__ float g_qkv[NTOK*QKVN];
__device__ float g_scores[(size_t)NBH*SEQ*SEQ];
__device__ float g_u[NTOK*HID2];
__device__ __nv_bfloat16 g_a2[(size_t)NTOK*(2*KPAD_H)];
#define B2_QKV_SZ ((size_t)1536*1024)
#define B2_WOUT_SZ ((size_t)512*1024)
#define B2_W0_SZ ((size_t)W0_NPAD*1024)
#define B2_W1_SZ ((size_t)512*1408)
#define B2_LAYER (B2_QKV_SZ+B2_WOUT_SZ+B2_W0_SZ+B2_W1_SZ)
__device__ __nv_bfloat16 g_b2[B2_LAYER*NDEPTH];

// ---------------- helpers ---------------------------------------------------
__device__ __forceinline__ uint32_t smem_u32(const void* p) {
    uint32_t a;
    asm("{ .reg .u64 t; cvta.to.shared.u64 t, %1; cvt.u32.u64 %0, t; }" : "=r"(a) : "l"(p));
    return a;
}
#define LDSM4(r0, r1, r2, r3, addr) \
    asm volatile("ldmatrix.sync.aligned.m8n8.x4.shared.b16 {%0,%1,%2,%3}, [%4];" \
        : "=r"(r0), "=r"(r1), "=r"(r2), "=r"(r3) : "r"(addr))
#define MMA16816(d, a, b) \
    asm volatile("mma.sync.aligned.m16n8k16.row.col.f32.bf16.bf16.f32 " \
        "{%0,%1,%2,%3},{%4,%5,%6,%7},{%8,%9},{%0,%1,%2,%3};" \
        : "+f"((d)[0]), "+f"((d)[1]), "+f"((d)[2]), "+f"((d)[3]) \
        : "r"((a)[0]), "r"((a)[1]), "r"((a)[2]), "r"((a)[3]), "r"((b)[0]), "r"((b)[1]))
#define CPA16(s, g) \
    asm volatile("cp.async.cg.shared.global [%0], [%1], 16;" :: "r"(s), "l"(g))
#define CPA_COMMIT asm volatile("cp.async.commit_group;" ::: "memory")
#define CPA_WAIT(n) asm volatile("cp.async.wait_group %0;" :: "n"(n) : "memory")

__device__ __forceinline__ void split_bf16(float v, __nv_bfloat16& hi, __nv_bfloat16& lo) {
    hi = __float2bfloat16(v);
    lo = __float2bfloat16(v - __bfloat162float(hi));
}

// ---------------- HMMA GEMM: C[M,Nact] = A2 @ B2^T (3-pass bf16 split) -----
// A2: [M, 2*Kpad] bf16 (hi|lo), B2: [Npad, 2*Kpad] bf16 (K-major, hi|lo)
// CTA tile 128x256, warp tile 64x64, BK=32, 3-stage cp.async pipeline.
#define APITCH 40                     /* bf16 per smem row (80B) */
#define ABUF (128*80)                 /* 10240 B per A stage */
#define BBUF (256*80)                 /* 20480 B per B stage */
#define BOFF (3*ABUF)                 /* B region start: 30720 */
#define GEMM_SMEM (3*(ABUF+BBUF))     /* 92160 B */
__global__ void __launch_bounds__(256)
gemm_mma(const __nv_bfloat16* __restrict__ A2, const __nv_bfloat16* __restrict__ B2,
         const float* __restrict__ bias, const float* __restrict__ res,
         float* __restrict__ C, int Nact, int Cs, int Kpad, int RES) {
    extern __shared__ __nv_bfloat16 dsm[];
    const uint32_t sbase = smem_u32(dsm);
    const int tid = threadIdx.x, lane = tid & 31, wid = tid >> 5;
    const int wm = wid & 1, wn = wid >> 1;          // 2(M) x 4(N) warps
    const int m0 = blockIdx.x * 128, n0 = blockIdx.y * 256;
    const int sA2 = 2 * Kpad;
    const int KC = Kpad >> 5;
    const int nsteps = 3 * KC;

    float acc[4][8][4];
#pragma unroll
    for (int a = 0; a < 4; a++)
#pragma unroll
        for (int b = 0; b < 8; b++)
#pragma unroll
            for (int c = 0; c < 4; c++) acc[a][b][c] = 0.f;

    // cp.async thread mapping: 16B chunks, 4 per 64B k-row
    const int rL = tid >> 2, cL = tid & 3;
    const uint32_t sA0 = sbase + rL * 80 + cL * 16;
    const uint32_t sB0 = sbase + BOFF + rL * 80 + cL * 16;
    const __nv_bfloat16* gA0 = A2 + (size_t)(m0 + rL) * sA2 + cL * 8;
    const __nv_bfloat16* gB0 = B2 + (size_t)(n0 + rL) * sA2 + cL * 8;

#define ISSUE(i) do { \
    int pass = ((i) >= 2 * KC) ? 2 : (((i) >= KC) ? 1 : 0); \
    int kc = (i) - pass * KC; \
    int aO = ((pass == 2) ? Kpad : 0) + kc * 32; \
    int bO = ((pass == 1) ? Kpad : 0) + kc * 32; \
    int bufi = (i) % 3; \
    uint32_t sa = sA0 + bufi * ABUF; \
    uint32_t sb = sB0 + bufi * BBUF; \
    CPA16(sa,        gA0 + aO); \
    CPA16(sa + 5120, gA0 + aO + (size_t)64 * sA2); \
    CPA16(sb,         gB0 + bO); \
    CPA16(sb + 5120,  gB0 + bO + (size_t)64 * sA2); \
    CPA16(sb + 10240, gB0 + bO + (size_t)128 * sA2); \
    CPA16(sb + 15360, gB0 + bO + (size_t)192 * sA2); \
    CPA_COMMIT; \
} while (0)

    // ldmatrix bases (stage 0)
    const int q = lane >> 3, rr = lane & 7;
    const uint32_t aBase = sbase +
        (uint32_t)((wm * 64 + (q & 1) * 8 + rr) * 80 + (q >> 1) * 16);
    const uint32_t bBase = sbase + BOFF +
        (uint32_t)((wn * 64 + (q >> 1) * 8 + rr) * 80 + (q & 1) * 16);

    ISSUE(0);
    ISSUE(1);

    for (int i = 0; i < nsteps; i++) {
        if (i == nsteps - 1) CPA_WAIT(0); else CPA_WAIT(1);
        __syncthreads();
        if (i + 2 < nsteps) ISSUE(i + 2);
        const int buf = i % 3;
        const uint32_t aB = aBase + buf * ABUF;
        const uint32_t bB = bBase + buf * BBUF;
#pragma unroll
        for (int kk = 0; kk < 2; kk++) {
            uint32_t af[4][4];
#pragma unroll
            for (int mi = 0; mi < 4; mi++)
                LDSM4(af[mi][0], af[mi][1], af[mi][2], af[mi][3],
                      aB + mi * 1280 + kk * 32);
            uint32_t bfr[8][2];
#pragma unroll
            for (int g = 0; g < 4; g++) {
                uint32_t t0, t1, t2, t3;
                LDSM4(t0, t1, t2, t3, bB + g * 1280 + kk * 32);
                bfr[2 * g][0] = t0;     bfr[2 * g][1] = t1;
                bfr[2 * g + 1][0] = t2; bfr[2 * g + 1][1] = t3;
            }
#pragma unroll
            for (int mi = 0; mi < 4; mi++)
#pragma unroll
                for (int ni = 0; ni < 8; ni++)
                    MMA16816(acc[mi][ni], af[mi], bfr[ni]);
        }
    }

    // epilogue
#pragma unroll
    for (int mi = 0; mi < 4; mi++) {
        int r0 = m0 + wm * 64 + mi * 16 + (lane >> 2);
        float* cr0 = C + (size_t)r0 * Cs;
        float* cr1 = C + (size_t)(r0 + 8) * Cs;
        const float* rr0 = res + (size_t)r0 * Cs;
        const float* rr1 = res + (size_t)(r0 + 8) * Cs;
#pragma unroll
        for (int ni = 0; ni < 8; ni++) {
            int c0 = n0 + wn * 64 + ni * 8 + (lane & 3) * 2;
            if (c0 < Nact) {
                float v0 = acc[mi][ni][0] + bias[c0];
                float v2 = acc[mi][ni][2] + bias[c0];
                if (RES) { v0 += rr0[c0]; v2 += rr1[c0]; }
                cr0[c0] = v0; cr1[c0] = v2;
            }
            if (c0 + 1 < Nact) {
                float v1 = acc[mi][ni][1] + bias[c0 + 1];
                float v3 = acc[mi][ni][3] + bias[c0 + 1];
                if (RES) { v1 += rr0[c0 + 1]; v3 += rr1[c0 + 1]; }
                cr0[c0 + 1] = v1; cr1[c0 + 1] = v3;
            }
        }
    }
}

// ---------------- weight conversion (batched over layers via blockIdx.z) ---
__global__ void convB_kernel(const float* __restrict__ W, __nv_bfloat16* __restrict__ dst,
                             int K, int N, int Kpad, size_t wStride, size_t dStride) {
    __shared__ float t[32][33];
    const float* Wl = W + blockIdx.z * wStride;
    __nv_bfloat16* dl = dst + blockIdx.z * dStride;
    int k0 = blockIdx.x * 32, n0 = blockIdx.y * 32;
    int tx = threadIdx.x, ty = threadIdx.y;
#pragma unroll
    for (int i = 0; i < 4; i++) {
        int k = k0 + ty + i * 8, n = n0 + tx;
        t[ty + i * 8][tx] = (k < K && n < N) ? Wl[(size_t)k * N + n] : 0.f;
    }
    __syncthreads();
#pragma unroll
    for (int i = 0; i < 4; i++) {
        int n = n0 + ty + i * 8, k = k0 + tx;
        float v = t[tx][ty + i * 8];
        __nv_bfloat16 hi, lo; split_bf16(v, hi, lo);
        dl[(size_t)n * 2 * Kpad + k] = hi;
        dl[(size_t)n * 2 * Kpad + Kpad + k] = lo;
    }
}

// ---------------- A conversion (layer 0 only) ------------------------------
__global__ void convA_kernel(const float* __restrict__ src, __nv_bfloat16* __restrict__ dst) {
    int m = blockIdx.x;
    const float* s = src + (size_t)m * EMBD;
    __nv_bfloat16* d = dst + (size_t)m * 1024;
    for (int k = threadIdx.x; k < 512; k += 128) {
        __nv_bfloat16 hi, lo; split_bf16(s[k], hi, lo);
        d[k] = hi; d[512 + k] = lo;
    }
}

// ---------------- tokenizer ------------------------------------------------
__global__ void tokenizer_kernel(const float* __restrict__ x,
                                 const float* __restrict__ tok_w,
                                 const float* __restrict__ tok_b,
                                 const float* __restrict__ cat_emb,
                                 float* __restrict__ h) {
    int t = blockIdx.x;
    int b = t / SEQ, s = t % SEQ;
    int e0 = threadIdx.x;
    const float* src;
    float scale = 1.0f;
    const float* brow = nullptr;
    if (s == 0) {
        src = tok_w;
    } else if (s <= NCONT) {
        src = tok_w + (size_t)s * EMBD;
        scale = x[(size_t)b * (NCAT + NCONT) + NCAT + (s - 1)];
        brow = tok_b + (size_t)(s - 1) * EMBD;
    } else {
        int c = s - (NCONT + 1);
        int idx = (int)x[(size_t)b * (NCAT + NCONT) + c] + 100 * c;
        src = cat_emb + (size_t)idx * EMBD;
        brow = tok_b + (size_t)(s - 1) * EMBD;
    }
    float* dst = h + (size_t)t * EMBD;
#pragma unroll
    for (int i = 0; i < 4; i++) {
        int e = e0 + i * 128;
        float v = src[e] * scale;
        if (brow) v += brow[e];
        dst[e] = v;
    }
}

// ---------------- layernorm -> bf16 hi/lo ----------------------------------
__global__ void ln_conv_kernel(const float* __restrict__ in,
                               const float* __restrict__ g,
                               const float* __restrict__ b,
                               __nv_bfloat16* __restrict__ out) {
    int row = blockIdx.x * 8 + threadIdx.y;
    if (row >= NTOK) return;
    const float* p = in + (size_t)row * EMBD;
    int lane = threadIdx.x;
    float v[16];
    float s = 0.f;
#pragma unroll
    for (int i = 0; i < 16; i++) { v[i] = p[lane + 32 * i]; s += v[i]; }
#pragma unroll
    for (int o = 16; o; o >>= 1) s += __shfl_xor_sync(0xffffffffu, s, o);
    float mean = s * (1.0f / EMBD);
    float vs = 0.f;
#pragma unroll
    for (int i = 0; i < 16; i++) { float d = v[i] - mean; vs += d * d; }
#pragma unroll
    for (int o = 16; o; o >>= 1) vs += __shfl_xor_sync(0xffffffffu, vs, o);
    float inv = rsqrtf(vs * (1.0f / EMBD) + 1e-5f);
    __nv_bfloat16* qo = out + (size_t)row * 1024;
#pragma unroll
    for (int i = 0; i < 16; i++) {
        int e = lane + 32 * i;
        float y = (v[i] - mean) * inv * g[e] + b[e];
        __nv_bfloat16 hi, lo; split_bf16(y, hi, lo);
        qo[e] = hi; qo[512 + e] = lo;
    }
}

// ---------------- attention scores -----------------------------------------
__global__ void scores_kernel(const float* __restrict__ qkv,
                              float* __restrict__ scores) {
    extern __shared__ float sm[];
    float* qs = sm;
    float* ks = sm + SEQ * 65;
    int bh = blockIdx.x;
    int b = bh / NHEADS, h = bh % NHEADS;
    const float* basep = qkv + (size_t)b * SEQ * QKVN + h * (3 * HDIM);
    int tid = threadIdx.x;
    for (int i = tid; i < SEQ * HDIM; i += 256) {
        int r = i / HDIM, d = i % HDIM;
        const float* row = basep + (size_t)r * QKVN;
        qs[r * 65 + d] = row[d];
        ks[r * 65 + d] = row[HDIM + d];
    }
    __syncthreads();
    const float scale = 22.62741699796952f;
    float* out = scores + (size_t)bh * SEQ * SEQ;
    for (int idx = tid; idx < SEQ * SEQ; idx += 256) {
        int i = idx / SEQ, j = idx % SEQ;
        const float* qi = qs + i * 65;
        const float* kj = ks + j * 65;
        float acc = 0.f;
#pragma unroll
        for (int d = 0; d < HDIM; d++) acc += qi[d] * kj[d];
        out[idx] = acc * scale;
    }
}

// ---------------- double softmax -------------------------------------------
__global__ void softmax2_kernel(float* __restrict__ scores) {
    int row = blockIdx.x * 8 + threadIdx.y;
    if (row >= NBH * SEQ) return;
    float* p = scores + (size_t)row * SEQ;
    int lane = threadIdx.x;
    float v[5];
    int cnt = 0;
    float mx = -1e30f;
    for (int j = lane; j < SEQ; j += 32) { v[cnt] = p[j]; mx = fmaxf(mx, v[cnt]); cnt++; }
#pragma unroll
    for (int o = 16; o; o >>= 1) mx = fmaxf(mx, __shfl_xor_sync(0xffffffffu, mx, o));
    float s = 0.f;
    for (int c = 0; c < cnt; c++) { v[c] = __expf(v[c] - mx); s += v[c]; }
#pragma unroll
    for (int o = 16; o; o >>= 1) s += __shfl_xor_sync(0xffffffffu, s, o);
    float inv = 1.0f / s;
    mx = -1e30f;
    for (int c = 0; c < cnt; c++) { v[c] *= inv; mx = fmaxf(mx, v[c]); }
#pragma unroll
    for (int o = 16; o; o >>= 1) mx = fmaxf(mx, __shfl_xor_sync(0xffffffffu, mx, o));
    s = 0.f;
    for (int c = 0; c < cnt; c++) { v[c] = __expf(v[c] - mx); s += v[c]; }
#pragma unroll
    for (int o = 16; o; o >>= 1) s += __shfl_xor_sync(0xffffffffu, s, o);
    inv = 1.0f / s;
    cnt = 0;
    for (int j = lane; j < SEQ; j += 32) { p[j] = v[cnt] * inv; cnt++; }
}

// ---------------- attn @ v -> A2 bf16 hi/lo --------------------------------
__global__ void av_conv_kernel(const float* __restrict__ qkv,
                               const float* __restrict__ scores,
                               __nv_bfloat16* __restrict__ a2) {
    extern __shared__ float sm[];
    float* attn = sm;
    float* vs = sm + SEQ * SEQ;
    int bh = blockIdx.x;
    int b = bh / NHEADS, h = bh % NHEADS;
    const float* vbase = qkv + (size_t)b * SEQ * QKVN + h * (3 * HDIM) + 2 * HDIM;
    int tid = threadIdx.y * 64 + threadIdx.x;
    const float* srow = scores + (size_t)bh * SEQ * SEQ;
    for (int i = tid; i < SEQ * SEQ; i += 256) attn[i] = srow[i];
    for (int i = tid; i < SEQ * HDIM; i += 256) {
        int r = i / HDIM, d = i % HDIM;
        vs[r * HDIM + d] = vbase[(size_t)r * QKVN + d];
    }
    __syncthreads();
    int d = threadIdx.x;
    int col = h * HDIM + d;
    for (int i = threadIdx.y; i < SEQ; i += 4) {
        const float* ar = attn + i * SEQ;
        float acc = 0.f;
        for (int j = 0; j < SEQ; j++) acc += ar[j] * vs[j * HDIM + d];
        __nv_bfloat16 hi, lo; split_bf16(acc, hi, lo);
        __nv_bfloat16* dRow = a2 + ((size_t)b * SEQ + i) * 1024;
        dRow[col] = hi; dRow[512 + col] = lo;
    }
}

// ---------------- ReGLU -> A2 bf16 hi/lo (Kpad=704) ------------------------
__global__ void reglu_conv_kernel(const float* __restrict__ u, __nv_bfloat16* __restrict__ a2) {
    int n = blockIdx.x;
    const float* un = u + (size_t)n * HID2;
    __nv_bfloat16* rn = a2 + (size_t)n * 1408;
    for (int j = threadIdx.x; j < KPAD_H; j += 256) {
        float v = (j < NHID) ? un[j] * fmaxf(un[NHID + j], 0.f) : 0.f;
        __nv_bfloat16 hi, lo; split_bf16(v, hi, lo);
        rn[j] = hi; rn[KPAD_H + j] = lo;
    }
}

// ---------------- extract CLS ----------------------------------------------
__global__ void extract_kernel(const float* __restrict__ h, float* __restrict__ out) {
    int b = blockIdx.x;
    int e = threadIdx.x;
    out[(size_t)b * EMBD + e] = h[(size_t)b * SEQ * EMBD + e];
}

// ---------------- host -----------------------------------------------------
extern "C" void kernel_launch(void* const* d_in, const int* in_sizes, int n_in,
                              void* d_out, int out_size) {
    (void)in_sizes; (void)n_in; (void)out_size;
    const float* x       = (const float*)d_in[0];
    const float* tok_w   = (const float*)d_in[1];
    const float* tok_b   = (const float*)d_in[2];
    const float* cat_emb = (const float*)d_in[3];
    const float* Wqkv    = (const float*)d_in[4];
    const float* bqkv    = (const float*)d_in[5];
    const float* Wout    = (const float*)d_in[6];
    const float* bout    = (const float*)d_in[7];
    const float* W0      = (const float*)d_in[8];
    const float* b0      = (const float*)d_in[9];
    const float* W1      = (const float*)d_in[10];
    const float* b1      = (const float*)d_in[11];
    const float* ln0_g   = (const float*)d_in[12];
    const float* ln0_b   = (const float*)d_in[13];
    const float* ln1_g   = (const float*)d_in[14];
    const float* ln1_b   = (const float*)d_in[15];
    float* out = (float*)d_out;

    float *ph, *pqkv, *pscores, *pu;
    __nv_bfloat16 *pa2, *pb2;
    cudaGetSymbolAddress((void**)&ph, g_h);
    cudaGetSymbolAddress((void**)&pqkv, g_qkv);
    cudaGetSymbolAddress((void**)&pscores, g_scores);
    cudaGetSymbolAddress((void**)&pu, g_u);
    cudaGetSymbolAddress((void**)&pa2, g_a2);
    cudaGetSymbolAddress((void**)&pb2, g_b2);

    const int SCORES_SMEM = 2 * SEQ * 65 * 4;
    const int AV_SMEM = (SEQ * SEQ + SEQ * HDIM) * 4;
    cudaFuncSetAttribute(scores_kernel, cudaFuncAttributeMaxDynamicSharedMemorySize, SCORES_SMEM);
    cudaFuncSetAttribute(av_conv_kernel, cudaFuncAttributeMaxDynamicSharedMemorySize, AV_SMEM);
    cudaFuncSetAttribute(gemm_mma, cudaFuncAttributeMaxDynamicSharedMemorySize, GEMM_SMEM);

    // weight conversion, batched over all layers
    {
        __nv_bfloat16* bq  = pb2;
        __nv_bfloat16* bo  = pb2 + B2_QKV_SZ;
        __nv_bfloat16* b0p = pb2 + B2_QKV_SZ + B2_WOUT_SZ;
        __nv_bfloat16* b1p = pb2 + B2_QKV_SZ + B2_WOUT_SZ + B2_W0_SZ;
        convB_kernel<<<dim3(16, 48, NDEPTH), dim3(32, 8)>>>(
            Wqkv, bq, 512, 1536, 512, (size_t)EMBD * QKVN, B2_LAYER);
        convB_kernel<<<dim3(16, 16, NDEPTH), dim3(32, 8)>>>(
            Wout, bo, 512, 512, 512, (size_t)EMBD * EMBD, B2_LAYER);
        convB_kernel<<<dim3(16, 48, NDEPTH), dim3(32, 8)>>>(
            W0, b0p, 512, HID2, 512, (size_t)EMBD * HID2, B2_LAYER);
        convB_kernel<<<dim3(22, 16, NDEPTH), dim3(32, 8)>>>(
            W1, b1p, NHID, 512, KPAD_H, (size_t)NHID * EMBD, B2_LAYER);
    }

    tokenizer_kernel<<<NTOK, 128>>>(x, tok_w, tok_b, cat_emb, ph);

    for (int L = 0; L < NDEPTH; L++) {
        __nv_bfloat16* bq  = pb2 + (size_t)L * B2_LAYER;
        __nv_bfloat16* bo  = bq + B2_QKV_SZ;
        __nv_bfloat16* b0p = bo + B2_WOUT_SZ;
        __nv_bfloat16* b1p = b0p + B2_W0_SZ;

        if (L == 0) {
            convA_kernel<<<NTOK, 128>>>(ph, pa2);
        } else {
            ln_conv_kernel<<<NTOK / 8, dim3(32, 8)>>>(ph, ln0_g + L * EMBD, ln0_b + L * EMBD, pa2);
        }
        gemm_mma<<<dim3(129, 6), 256, GEMM_SMEM>>>(pa2, bq, bqkv + (size_t)L * QKVN,
                                                   ph, pqkv, QKVN, QKVN, KPAD_E, 0);
        scores_kernel<<<NBH, 256, SCORES_SMEM>>>(pqkv, pscores);
        softmax2_kernel<<<NBH * SEQ / 8, dim3(32, 8)>>>(pscores);
        av_conv_kernel<<<NBH, dim3(64, 4), AV_SMEM>>>(pqkv, pscores, pa2);
        gemm_mma<<<dim3(129, 2), 256, GEMM_SMEM>>>(pa2, bo, bout + (size_t)L * EMBD,
                                                   ph, ph, EMBD, EMBD, KPAD_E, 1);
        ln_conv_kernel<<<NTOK / 8, dim3(32, 8)>>>(ph, ln1_g + L * EMBD, ln1_b + L * EMBD, pa2);
        gemm_mma<<<dim3(129, 6), 256, GEMM_SMEM>>>(pa2, b0p, b0 + (size_t)L * HID2,
                                                   ph, pu, HID2, HID2, KPAD_E, 0);
        reglu_conv_kernel<<<NTOK, 256>>>(pu, pa2);
        gemm_mma<<<dim3(129, 2), 256, GEMM_SMEM>>>(pa2, b1p, b1 + (size_t)L * EMBD,
                                                   ph, ph, EMBD, EMBD, KPAD_H, 1);
    }
    extract_kernel<<<BSZ, EMBD>>>(ph, out);
}

// round 5
// speedup vs baseline: 1.2300x; 1.2300x over previous
#include <cuda_runtime.h>
#include <cuda_bf16.h>
#include <cstdint>
#include <math.h>

#define EMBD 512
#define NHEADS 8
#define HDIM 64
#define NDEPTH 6
#define NCONT 100
#define NCAT 28
#define NHID 682
#define BSZ 128
#define SEQ 129
#define NTOK (BSZ*SEQ)      /* 16512 */
#define QKVN (3*EMBD)       /* 1536  */
#define HID2 (2*NHID)       /* 1364  */
#define NBH (BSZ*NHEADS)    /* 1024  */

#define KPAD_E 512
#define KPAD_H 704
#define W0_NPAD 1536

// ---------------- scratch (device globals) ---------------------------------
__device__ float g_h[NTOK*EMBD];
__device__ float g_qkv[NTOK*QKVN];
__device__ float g_scores[(size_t)NBH*SEQ*SEQ];
__device__ float g_u[NTOK*HID2];
__device__ __nv_bfloat16 g_a2[(size_t)NTOK*(2*KPAD_H)];
#define B2_QKV_SZ ((size_t)1536*1024)
#define B2_WOUT_SZ ((size_t)512*1024)
#define B2_W0_SZ ((size_t)W0_NPAD*1024)
#define B2_W1_SZ ((size_t)512*1408)
#define B2_LAYER (B2_QKV_SZ+B2_WOUT_SZ+B2_W0_SZ+B2_W1_SZ)
__device__ __nv_bfloat16 g_b2[B2_LAYER*NDEPTH];

// ---------------- helpers ---------------------------------------------------
__device__ __forceinline__ uint32_t smem_u32(const void* p) {
    uint32_t a;
    asm("{ .reg .u64 t; cvta.to.shared.u64 t, %1; cvt.u32.u64 %0, t; }" : "=r"(a) : "l"(p));
    return a;
}
#define LDSM4(r0, r1, r2, r3, addr) \
    asm volatile("ldmatrix.sync.aligned.m8n8.x4.shared.b16 {%0,%1,%2,%3}, [%4];" \
        : "=r"(r0), "=r"(r1), "=r"(r2), "=r"(r3) : "r"(addr))
#define MMA16816(d, a, b) \
    asm volatile("mma.sync.aligned.m16n8k16.row.col.f32.bf16.bf16.f32 " \
        "{%0,%1,%2,%3},{%4,%5,%6,%7},{%8,%9},{%0,%1,%2,%3};" \
        : "+f"((d)[0]), "+f"((d)[1]), "+f"((d)[2]), "+f"((d)[3]) \
        : "r"((a)[0]), "r"((a)[1]), "r"((a)[2]), "r"((a)[3]), "r"((b)[0]), "r"((b)[1]))
#define CPA16(s, g) \
    asm volatile("cp.async.cg.shared.global [%0], [%1], 16;" :: "r"(s), "l"(g))
#define CPA_COMMIT asm volatile("cp.async.commit_group;" ::: "memory")
#define CPA_WAIT(n) asm volatile("cp.async.wait_group %0;" :: "n"(n) : "memory")

__device__ __forceinline__ void split_bf16(float v, __nv_bfloat16& hi, __nv_bfloat16& lo) {
    hi = __float2bfloat16(v);
    lo = __float2bfloat16(v - __bfloat162float(hi));
}

// ---------------- HMMA GEMM: C[M,Nact] = A2 @ B2^T (3-pass bf16 split) -----
// A2: [M, 2*Kpad] bf16 (hi|lo), B2: [Npad, 2*Kpad] bf16 (K-major, hi|lo)
// CTA tile 128x128, warp tile 64x32, BK=32, 3-stage cp.async, 2 CTAs/SM.
#define ABUF (128*80)                 /* 10240 B per A stage */
#define BBUF (128*80)                 /* 10240 B per B stage */
#define BOFF (3*ABUF)                 /* 30720 */
#define GEMM_SMEM (3*(ABUF+BBUF))     /* 61440 B */
__global__ void __launch_bounds__(256, 2)
gemm_mma(const __nv_bfloat16* __restrict__ A2, const __nv_bfloat16* __restrict__ B2,
         const float* __restrict__ bias, const float* __restrict__ res,
         float* __restrict__ C, int Nact, int Cs, int Kpad, int RES) {
    extern __shared__ __nv_bfloat16 dsm[];
    const uint32_t sbase = smem_u32(dsm);
    const int tid = threadIdx.x, lane = tid & 31, wid = tid >> 5;
    const int wm = wid & 1, wn = wid >> 1;          // 2(M) x 4(N) warps
    const int m0 = blockIdx.x * 128, n0 = blockIdx.y * 128;
    const int sA2 = 2 * Kpad;
    const int KC = Kpad >> 5;
    const int nsteps = 3 * KC;

    float acc[4][4][4];
#pragma unroll
    for (int a = 0; a < 4; a++)
#pragma unroll
        for (int b = 0; b < 4; b++)
#pragma unroll
            for (int c = 0; c < 4; c++) acc[a][b][c] = 0.f;

    // cp.async thread mapping: 16B chunks, 4 per 64B k-row, rows 0..63 (+64)
    const int rL = tid >> 2, cL = tid & 3;
    const uint32_t sA0 = sbase + rL * 80 + cL * 16;
    const uint32_t sB0 = sbase + BOFF + rL * 80 + cL * 16;
    const __nv_bfloat16* gA0 = A2 + (size_t)(m0 + rL) * sA2 + cL * 8;
    const __nv_bfloat16* gB0 = B2 + (size_t)(n0 + rL) * sA2 + cL * 8;

#define ISSUE(i) do { \
    int pass = ((i) >= 2 * KC) ? 2 : (((i) >= KC) ? 1 : 0); \
    int kc = (i) - pass * KC; \
    int aO = ((pass == 2) ? Kpad : 0) + kc * 32; \
    int bO = ((pass == 1) ? Kpad : 0) + kc * 32; \
    int bufi = (i) % 3; \
    uint32_t sa = sA0 + bufi * ABUF; \
    uint32_t sb = sB0 + bufi * BBUF; \
    CPA16(sa,        gA0 + aO); \
    CPA16(sa + 5120, gA0 + aO + (size_t)64 * sA2); \
    CPA16(sb,        gB0 + bO); \
    CPA16(sb + 5120, gB0 + bO + (size_t)64 * sA2); \
    CPA_COMMIT; \
} while (0)

    // ldmatrix bases (stage 0)
    const int q = lane >> 3, rr = lane & 7;
    const uint32_t aBase = sbase +
        (uint32_t)((wm * 64 + (q & 1) * 8 + rr) * 80 + (q >> 1) * 16);
    const uint32_t bBase = sbase + BOFF +
        (uint32_t)((wn * 32 + (q >> 1) * 8 + rr) * 80 + (q & 1) * 16);

    ISSUE(0);
    ISSUE(1);

    for (int i = 0; i < nsteps; i++) {
        if (i == nsteps - 1) CPA_WAIT(0); else CPA_WAIT(1);
        __syncthreads();
        if (i + 2 < nsteps) ISSUE(i + 2);
        const int buf = i % 3;
        const uint32_t aB = aBase + buf * ABUF;
        const uint32_t bB = bBase + buf * BBUF;
#pragma unroll
        for (int kk = 0; kk < 2; kk++) {
            uint32_t af[4][4];
#pragma unroll
            for (int mi = 0; mi < 4; mi++)
                LDSM4(af[mi][0], af[mi][1], af[mi][2], af[mi][3],
                      aB + mi * 1280 + kk * 32);
            uint32_t bfr[4][2];
#pragma unroll
            for (int g = 0; g < 2; g++) {
                uint32_t t0, t1, t2, t3;
                LDSM4(t0, t1, t2, t3, bB + g * 1280 + kk * 32);
                bfr[2 * g][0] = t0;     bfr[2 * g][1] = t1;
                bfr[2 * g + 1][0] = t2; bfr[2 * g + 1][1] = t3;
            }
#pragma unroll
            for (int mi = 0; mi < 4; mi++)
#pragma unroll
                for (int ni = 0; ni < 4; ni++)
                    MMA16816(acc[mi][ni], af[mi], bfr[ni]);
        }
    }

    // epilogue
#pragma unroll
    for (int mi = 0; mi < 4; mi++) {
        int r0 = m0 + wm * 64 + mi * 16 + (lane >> 2);
        float* cr0 = C + (size_t)r0 * Cs;
        float* cr1 = C + (size_t)(r0 + 8) * Cs;
        const float* rr0 = res + (size_t)r0 * Cs;
        const float* rr1 = res + (size_t)(r0 + 8) * Cs;
#pragma unroll
        for (int ni = 0; ni < 4; ni++) {
            int c0 = n0 + wn * 32 + ni * 8 + (lane & 3) * 2;
            if (c0 < Nact) {
                float v0 = acc[mi][ni][0] + bias[c0];
                float v2 = acc[mi][ni][2] + bias[c0];
                if (RES) { v0 += rr0[c0]; v2 += rr1[c0]; }
                cr0[c0] = v0; cr1[c0] = v2;
            }
            if (c0 + 1 < Nact) {
                float v1 = acc[mi][ni][1] + bias[c0 + 1];
                float v3 = acc[mi][ni][3] + bias[c0 + 1];
                if (RES) { v1 += rr0[c0 + 1]; v3 += rr1[c0 + 1]; }
                cr0[c0 + 1] = v1; cr1[c0 + 1] = v3;
            }
        }
    }
}

// ---------------- weight conversion (batched over layers via blockIdx.z) ---
__global__ void convB_kernel(const float* __restrict__ W, __nv_bfloat16* __restrict__ dst,
                             int K, int N, int Kpad, size_t wStride, size_t dStride) {
    __shared__ float t[32][33];
    const float* Wl = W + blockIdx.z * wStride;
    __nv_bfloat16* dl = dst + blockIdx.z * dStride;
    int k0 = blockIdx.x * 32, n0 = blockIdx.y * 32;
    int tx = threadIdx.x, ty = threadIdx.y;
#pragma unroll
    for (int i = 0; i < 4; i++) {
        int k = k0 + ty + i * 8, n = n0 + tx;
        t[ty + i * 8][tx] = (k < K && n < N) ? Wl[(size_t)k * N + n] : 0.f;
    }
    __syncthreads();
#pragma unroll
    for (int i = 0; i < 4; i++) {
        int n = n0 + ty + i * 8, k = k0 + tx;
        float v = t[tx][ty + i * 8];
        __nv_bfloat16 hi, lo; split_bf16(v, hi, lo);
        dl[(size_t)n * 2 * Kpad + k] = hi;
        dl[(size_t)n * 2 * Kpad + Kpad + k] = lo;
    }
}

// ---------------- A conversion (layer 0 only) ------------------------------
__global__ void convA_kernel(const float* __restrict__ src, __nv_bfloat16* __restrict__ dst) {
    int m = blockIdx.x;
    const float* s = src + (size_t)m * EMBD;
    __nv_bfloat16* d = dst + (size_t)m * 1024;
    for (int k = threadIdx.x; k < 512; k += 128) {
        __nv_bfloat16 hi, lo; split_bf16(s[k], hi, lo);
        d[k] = hi; d[512 + k] = lo;
    }
}

// ---------------- tokenizer ------------------------------------------------
__global__ void tokenizer_kernel(const float* __restrict__ x,
                                 const float* __restrict__ tok_w,
                                 const float* __restrict__ tok_b,
                                 const float* __restrict__ cat_emb,
                                 float* __restrict__ h) {
    int t = blockIdx.x;
    int b = t / SEQ, s = t % SEQ;
    int e0 = threadIdx.x;
    const float* src;
    float scale = 1.0f;
    const float* brow = nullptr;
    if (s == 0) {
        src = tok_w;
    } else if (s <= NCONT) {
        src = tok_w + (size_t)s * EMBD;
        scale = x[(size_t)b * (NCAT + NCONT) + NCAT + (s - 1)];
        brow = tok_b + (size_t)(s - 1) * EMBD;
    } else {
        int c = s - (NCONT + 1);
        int idx = (int)x[(size_t)b * (NCAT + NCONT) + c] + 100 * c;
        src = cat_emb + (size_t)idx * EMBD;
        brow = tok_b + (size_t)(s - 1) * EMBD;
    }
    float* dst = h + (size_t)t * EMBD;
#pragma unroll
    for (int i = 0; i < 4; i++) {
        int e = e0 + i * 128;
        float v = src[e] * scale;
        if (brow) v += brow[e];
        dst[e] = v;
    }
}

// ---------------- layernorm -> bf16 hi/lo ----------------------------------
__global__ void ln_conv_kernel(const float* __restrict__ in,
                               const float* __restrict__ g,
                               const float* __restrict__ b,
                               __nv_bfloat16* __restrict__ out) {
    int row = blockIdx.x * 8 + threadIdx.y;
    if (row >= NTOK) return;
    const float* p = in + (size_t)row * EMBD;
    int lane = threadIdx.x;
    float v[16];
    float s = 0.f;
#pragma unroll
    for (int i = 0; i < 16; i++) { v[i] = p[lane + 32 * i]; s += v[i]; }
#pragma unroll
    for (int o = 16; o; o >>= 1) s += __shfl_xor_sync(0xffffffffu, s, o);
    float mean = s * (1.0f / EMBD);
    float vs = 0.f;
#pragma unroll
    for (int i = 0; i < 16; i++) { float d = v[i] - mean; vs += d * d; }
#pragma unroll
    for (int o = 16; o; o >>= 1) vs += __shfl_xor_sync(0xffffffffu, vs, o);
    float inv = rsqrtf(vs * (1.0f / EMBD) + 1e-5f);
    __nv_bfloat16* qo = out + (size_t)row * 1024;
#pragma unroll
    for (int i = 0; i < 16; i++) {
        int e = lane + 32 * i;
        float y = (v[i] - mean) * inv * g[e] + b[e];
        __nv_bfloat16 hi, lo; split_bf16(y, hi, lo);
        qo[e] = hi; qo[512 + e] = lo;
    }
}

// ---------------- attention scores -----------------------------------------
__global__ void scores_kernel(const float* __restrict__ qkv,
                              float* __restrict__ scores) {
    extern __shared__ float sm[];
    float* qs = sm;
    float* ks = sm + SEQ * 65;
    int bh = blockIdx.x;
    int b = bh / NHEADS, h = bh % NHEADS;
    const float* basep = qkv + (size_t)b * SEQ * QKVN + h * (3 * HDIM);
    int tid = threadIdx.x;
    for (int i = tid; i < SEQ * HDIM; i += 256) {
        int r = i / HDIM, d = i % HDIM;
        const float* row = basep + (size_t)r * QKVN;
        qs[r * 65 + d] = row[d];
        ks[r * 65 + d] = row[HDIM + d];
    }
    __syncthreads();
    const float scale = 22.62741699796952f;
    float* out = scores + (size_t)bh * SEQ * SEQ;
    for (int idx = tid; idx < SEQ * SEQ; idx += 256) {
        int i = idx / SEQ, j = idx % SEQ;
        const float* qi = qs + i * 65;
        const float* kj = ks + j * 65;
        float acc = 0.f;
#pragma unroll
        for (int d = 0; d < HDIM; d++) acc += qi[d] * kj[d];
        out[idx] = acc * scale;
    }
}

// ---------------- double softmax -------------------------------------------
__global__ void softmax2_kernel(float* __restrict__ scores) {
    int row = blockIdx.x * 8 + threadIdx.y;
    if (row >= NBH * SEQ) return;
    float* p = scores + (size_t)row * SEQ;
    int lane = threadIdx.x;
    float v[5];
    int cnt = 0;
    float mx = -1e30f;
    for (int j = lane; j < SEQ; j += 32) { v[cnt] = p[j]; mx = fmaxf(mx, v[cnt]); cnt++; }
#pragma unroll
    for (int o = 16; o; o >>= 1) mx = fmaxf(mx, __shfl_xor_sync(0xffffffffu, mx, o));
    float s = 0.f;
    for (int c = 0; c < cnt; c++) { v[c] = __expf(v[c] - mx); s += v[c]; }
#pragma unroll
    for (int o = 16; o; o >>= 1) s += __shfl_xor_sync(0xffffffffu, s, o);
    float inv = 1.0f / s;
    mx = -1e30f;
    for (int c = 0; c < cnt; c++) { v[c] *= inv; mx = fmaxf(mx, v[c]); }
#pragma unroll
    for (int o = 16; o; o >>= 1) mx = fmaxf(mx, __shfl_xor_sync(0xffffffffu, mx, o));
    s = 0.f;
    for (int c = 0; c < cnt; c++) { v[c] = __expf(v[c] - mx); s += v[c]; }
#pragma unroll
    for (int o = 16; o; o >>= 1) s += __shfl_xor_sync(0xffffffffu, s, o);
    inv = 1.0f / s;
    cnt = 0;
    for (int j = lane; j < SEQ; j += 32) { p[j] = v[cnt] * inv; cnt++; }
}

// ---------------- attn @ v -> A2 bf16 hi/lo --------------------------------
__global__ void av_conv_kernel(const float* __restrict__ qkv,
                               const float* __restrict__ scores,
                               __nv_bfloat16* __restrict__ a2) {
    extern __shared__ float sm[];
    float* attn = sm;
    float* vs = sm + SEQ * SEQ;
    int bh = blockIdx.x;
    int b = bh / NHEADS, h = bh % NHEADS;
    const float* vbase = qkv + (size_t)b * SEQ * QKVN + h * (3 * HDIM) + 2 * HDIM;
    int tid = threadIdx.y * 64 + threadIdx.x;
    const float* srow = scores + (size_t)bh * SEQ * SEQ;
    for (int i = tid; i < SEQ * SEQ; i += 256) attn[i] = srow[i];
    for (int i = tid; i < SEQ * HDIM; i += 256) {
        int r = i / HDIM, d = i % HDIM;
        vs[r * HDIM + d] = vbase[(size_t)r * QKVN + d];
    }
    __syncthreads();
    int d = threadIdx.x;
    int col = h * HDIM + d;
    for (int i = threadIdx.y; i < SEQ; i += 4) {
        const float* ar = attn + i * SEQ;
        float acc = 0.f;
        for (int j = 0; j < SEQ; j++) acc += ar[j] * vs[j * HDIM + d];
        __nv_bfloat16 hi, lo; split_bf16(acc, hi, lo);
        __nv_bfloat16* dRow = a2 + ((size_t)b * SEQ + i) * 1024;
        dRow[col] = hi; dRow[512 + col] = lo;
    }
}

// ---------------- ReGLU -> A2 bf16 hi/lo (Kpad=704) ------------------------
__global__ void reglu_conv_kernel(const float* __restrict__ u, __nv_bfloat16* __restrict__ a2) {
    int n = blockIdx.x;
    const float* un = u + (size_t)n * HID2;
    __nv_bfloat16* rn = a2 + (size_t)n * 1408;
    for (int j = threadIdx.x; j < KPAD_H; j += 256) {
        float v = (j < NHID) ? un[j] * fmaxf(un[NHID + j], 0.f) : 0.f;
        __nv_bfloat16 hi, lo; split_bf16(v, hi, lo);
        rn[j] = hi; rn[KPAD_H + j] = lo;
    }
}

// ---------------- extract CLS ----------------------------------------------
__global__ void extract_kernel(const float* __restrict__ h, float* __restrict__ out) {
    int b = blockIdx.x;
    int e = threadIdx.x;
    out[(size_t)b * EMBD + e] = h[(size_t)b * SEQ * EMBD + e];
}

// ---------------- host -----------------------------------------------------
extern "C" void kernel_launch(void* const* d_in, const int* in_sizes, int n_in,
                              void* d_out, int out_size) {
    (void)in_sizes; (void)n_in; (void)out_size;
    const float* x       = (const float*)d_in[0];
    const float* tok_w   = (const float*)d_in[1];
    const float* tok_b   = (const float*)d_in[2];
    const float* cat_emb = (const float*)d_in[3];
    const float* Wqkv    = (const float*)d_in[4];
    const float* bqkv    = (const float*)d_in[5];
    const float* Wout    = (const float*)d_in[6];
    const float* bout    = (const float*)d_in[7];
    const float* W0      = (const float*)d_in[8];
    const float* b0      = (const float*)d_in[9];
    const float* W1      = (const float*)d_in[10];
    const float* b1      = (const float*)d_in[11];
    const float* ln0_g   = (const float*)d_in[12];
    const float* ln0_b   = (const float*)d_in[13];
    const float* ln1_g   = (const float*)d_in[14];
    const float* ln1_b   = (const float*)d_in[15];
    float* out = (float*)d_out;

    float *ph, *pqkv, *pscores, *pu;
    __nv_bfloat16 *pa2, *pb2;
    cudaGetSymbolAddress((void**)&ph, g_h);
    cudaGetSymbolAddress((void**)&pqkv, g_qkv);
    cudaGetSymbolAddress((void**)&pscores, g_scores);
    cudaGetSymbolAddress((void**)&pu, g_u);
    cudaGetSymbolAddress((void**)&pa2, g_a2);
    cudaGetSymbolAddress((void**)&pb2, g_b2);

    const int SCORES_SMEM = 2 * SEQ * 65 * 4;
    const int AV_SMEM = (SEQ * SEQ + SEQ * HDIM) * 4;
    cudaFuncSetAttribute(scores_kernel, cudaFuncAttributeMaxDynamicSharedMemorySize, SCORES_SMEM);
    cudaFuncSetAttribute(av_conv_kernel, cudaFuncAttributeMaxDynamicSharedMemorySize, AV_SMEM);
    cudaFuncSetAttribute(gemm_mma, cudaFuncAttributeMaxDynamicSharedMemorySize, GEMM_SMEM);

    // weight conversion, batched over all layers
    {
        __nv_bfloat16* bq  = pb2;
        __nv_bfloat16* bo  = pb2 + B2_QKV_SZ;
        __nv_bfloat16* b0p = pb2 + B2_QKV_SZ + B2_WOUT_SZ;
        __nv_bfloat16* b1p = pb2 + B2_QKV_SZ + B2_WOUT_SZ + B2_W0_SZ;
        convB_kernel<<<dim3(16, 48, NDEPTH), dim3(32, 8)>>>(
            Wqkv, bq, 512, 1536, 512, (size_t)EMBD * QKVN, B2_LAYER);
        convB_kernel<<<dim3(16, 16, NDEPTH), dim3(32, 8)>>>(
            Wout, bo, 512, 512, 512, (size_t)EMBD * EMBD, B2_LAYER);
        convB_kernel<<<dim3(16, 48, NDEPTH), dim3(32, 8)>>>(
            W0, b0p, 512, HID2, 512, (size_t)EMBD * HID2, B2_LAYER);
        convB_kernel<<<dim3(22, 16, NDEPTH), dim3(32, 8)>>>(
            W1, b1p, NHID, 512, KPAD_H, (size_t)NHID * EMBD, B2_LAYER);
    }

    tokenizer_kernel<<<NTOK, 128>>>(x, tok_w, tok_b, cat_emb, ph);

    for (int L = 0; L < NDEPTH; L++) {
        __nv_bfloat16* bq  = pb2 + (size_t)L * B2_LAYER;
        __nv_bfloat16* bo  = bq + B2_QKV_SZ;
        __nv_bfloat16* b0p = bo + B2_WOUT_SZ;
        __nv_bfloat16* b1p = b0p + B2_W0_SZ;

        if (L == 0) {
            convA_kernel<<<NTOK, 128>>>(ph, pa2);
        } else {
            ln_conv_kernel<<<NTOK / 8, dim3(32, 8)>>>(ph, ln0_g + L * EMBD, ln0_b + L * EMBD, pa2);
        }
        gemm_mma<<<dim3(129, 12), 256, GEMM_SMEM>>>(pa2, bq, bqkv + (size_t)L * QKVN,
                                                    ph, pqkv, QKVN, QKVN, KPAD_E, 0);
        scores_kernel<<<NBH, 256, SCORES_SMEM>>>(pqkv, pscores);
        softmax2_kernel<<<NBH * SEQ / 8, dim3(32, 8)>>>(pscores);
        av_conv_kernel<<<NBH, dim3(64, 4), AV_SMEM>>>(pqkv, pscores, pa2);
        gemm_mma<<<dim3(129, 4), 256, GEMM_SMEM>>>(pa2, bo, bout + (size_t)L * EMBD,
                                                   ph, ph, EMBD, EMBD, KPAD_E, 1);
        ln_conv_kernel<<<NTOK / 8, dim3(32, 8)>>>(ph, ln1_g + L * EMBD, ln1_b + L * EMBD, pa2);
        gemm_mma<<<dim3(129, 11), 256, GEMM_SMEM>>>(pa2, b0p, b0 + (size_t)L * HID2,
                                                    ph, pu, HID2, HID2, KPAD_E, 0);
        reglu_conv_kernel<<<NTOK, 256>>>(pu, pa2);
        gemm_mma<<<dim3(129, 4), 256, GEMM_SMEM>>>(pa2, b1p, b1 + (size_t)L * EMBD,
                                                   ph, ph, EMBD, EMBD, KPAD_H, 1);
    }
    extract_kernel<<<BSZ, EMBD>>>(ph, out);
}

// round 6
// speedup vs baseline: 1.3065x; 1.0622x over previous
#include <cuda_runtime.h>
#include <cuda_bf16.h>
#include <cstdint>
#include <math.h>

#define EMBD 512
#define NHEADS 8
#define HDIM 64
#define NDEPTH 6
#define NCONT 100
#define NCAT 28
#define NHID 682
#define BSZ 128
#define SEQ 129
#define NTOK (BSZ*SEQ)      /* 16512 */
#define QKVN (3*EMBD)       /* 1536  */
#define HID2 (2*NHID)       /* 1364  */
#define NBH (BSZ*NHEADS)    /* 1024  */

#define KPAD_E 512
#define KPAD_H 704
#define W0_NPAD 1536

// ---------------- scratch (device globals) ---------------------------------
__device__ float g_h[NTOK*EMBD];
__device__ float g_qkv[NTOK*QKVN];
__device__ float g_scores[(size_t)NBH*SEQ*SEQ];
__device__ float g_u[NTOK*HID2];
__device__ __nv_bfloat16 g_a2[(size_t)NTOK*(2*KPAD_H)];
#define B2_QKV_SZ ((size_t)1536*1024)
#define B2_WOUT_SZ ((size_t)512*1024)
#define B2_W0_SZ ((size_t)W0_NPAD*1024)
#define B2_W1_SZ ((size_t)512*1408)
#define B2_LAYER (B2_QKV_SZ+B2_WOUT_SZ+B2_W0_SZ+B2_W1_SZ)
__device__ __nv_bfloat16 g_b2[B2_LAYER*NDEPTH];

// ---------------- helpers ---------------------------------------------------
__device__ __forceinline__ uint32_t smem_u32(const void* p) {
    uint32_t a;
    asm("{ .reg .u64 t; cvta.to.shared.u64 t, %1; cvt.u32.u64 %0, t; }" : "=r"(a) : "l"(p));
    return a;
}
#define LDSM4(r0, r1, r2, r3, addr) \
    asm volatile("ldmatrix.sync.aligned.m8n8.x4.shared.b16 {%0,%1,%2,%3}, [%4];" \
        : "=r"(r0), "=r"(r1), "=r"(r2), "=r"(r3) : "r"(addr))
#define MMA16816(d, a, b) \
    asm volatile("mma.sync.aligned.m16n8k16.row.col.f32.bf16.bf16.f32 " \
        "{%0,%1,%2,%3},{%4,%5,%6,%7},{%8,%9},{%0,%1,%2,%3};" \
        : "+f"((d)[0]), "+f"((d)[1]), "+f"((d)[2]), "+f"((d)[3]) \
        : "r"((a)[0]), "r"((a)[1]), "r"((a)[2]), "r"((a)[3]), "r"((b)[0]), "r"((b)[1]))
#define CPA16(s, g) \
    asm volatile("cp.async.cg.shared.global [%0], [%1], 16;" :: "r"(s), "l"(g))
#define CPA_COMMIT asm volatile("cp.async.commit_group;" ::: "memory")
#define CPA_WAIT(n) asm volatile("cp.async.wait_group %0;" :: "n"(n) : "memory")

__device__ __forceinline__ void split_bf16(float v, __nv_bfloat16& hi, __nv_bfloat16& lo) {
    hi = __float2bfloat16(v);
    lo = __float2bfloat16(v - __bfloat162float(hi));
}

// ---------------- HMMA GEMM: C[M,Nact] = A2 @ B2^T (3-pass bf16 split) -----
// A2: [M, 2*Kpad] bf16 (hi|lo), B2: [Npad, 2*Kpad] bf16 (K-major, hi|lo)
// CTA tile 128x128, warp tile 64x32, BK=64, 3-stage cp.async, 2 CTAs/SM.
#define PITCH 144                     /* bytes per smem row (128 data + 16 pad) */
#define ABUF (128*PITCH)              /* 18432 B per A stage */
#define BBUF (128*PITCH)              /* 18432 B per B stage */
#define BOFF (3*ABUF)                 /* 55296 */
#define GEMM_SMEM (3*(ABUF+BBUF))     /* 110592 B */
__global__ void __launch_bounds__(256, 2)
gemm_mma(const __nv_bfloat16* __restrict__ A2, const __nv_bfloat16* __restrict__ B2,
         const float* __restrict__ bias, const float* __restrict__ res,
         float* __restrict__ C, int Nact, int Cs, int Kpad, int RES) {
    extern __shared__ __nv_bfloat16 dsm[];
    const uint32_t sbase = smem_u32(dsm);
    const int tid = threadIdx.x, lane = tid & 31, wid = tid >> 5;
    const int wm = wid & 1, wn = wid >> 1;          // 2(M) x 4(N) warps
    const int m0 = blockIdx.x * 128, n0 = blockIdx.y * 128;
    const int sA2 = 2 * Kpad;
    const int KC = Kpad >> 6;                        // BK=64 chunks per pass
    const int nsteps = 3 * KC;

    float acc[4][4][4];
#pragma unroll
    for (int a = 0; a < 4; a++)
#pragma unroll
        for (int b = 0; b < 4; b++)
#pragma unroll
            for (int c = 0; c < 4; c++) acc[a][b][c] = 0.f;

    // cp.async thread mapping: 16B chunks, 8 per 128B k-row, rows 0..31 (+32,+64,+96)
    const int rT = tid >> 3, cT = tid & 7;
    const uint32_t sA0 = sbase + rT * PITCH + cT * 16;
    const uint32_t sB0 = sbase + BOFF + rT * PITCH + cT * 16;
    const __nv_bfloat16* gA0 = A2 + (size_t)(m0 + rT) * sA2 + cT * 8;
    const __nv_bfloat16* gB0 = B2 + (size_t)(n0 + rT) * sA2 + cT * 8;

#define ISSUE(i) do { \
    int pass = ((i) >= 2 * KC) ? 2 : (((i) >= KC) ? 1 : 0); \
    int kc = (i) - pass * KC; \
    int aO = ((pass == 2) ? Kpad : 0) + kc * 64; \
    int bO = ((pass == 1) ? Kpad : 0) + kc * 64; \
    int bufi = (i) % 3; \
    uint32_t sa = sA0 + bufi * ABUF; \
    uint32_t sb = sB0 + bufi * BBUF; \
    CPA16(sa,             gA0 + aO); \
    CPA16(sa + 32*PITCH,  gA0 + aO + (size_t)32 * sA2); \
    CPA16(sa + 64*PITCH,  gA0 + aO + (size_t)64 * sA2); \
    CPA16(sa + 96*PITCH,  gA0 + aO + (size_t)96 * sA2); \
    CPA16(sb,             gB0 + bO); \
    CPA16(sb + 32*PITCH,  gB0 + bO + (size_t)32 * sA2); \
    CPA16(sb + 64*PITCH,  gB0 + bO + (size_t)64 * sA2); \
    CPA16(sb + 96*PITCH,  gB0 + bO + (size_t)96 * sA2); \
    CPA_COMMIT; \
} while (0)

    // ldmatrix bases (stage 0)
    const int q = lane >> 3, rr = lane & 7;
    const uint32_t aBase = sbase +
        (uint32_t)((wm * 64 + (q & 1) * 8 + rr) * PITCH + (q >> 1) * 16);
    const uint32_t bBase = sbase + BOFF +
        (uint32_t)((wn * 32 + (q >> 1) * 8 + rr) * PITCH + (q & 1) * 16);

    ISSUE(0);
    ISSUE(1);

    for (int i = 0; i < nsteps; i++) {
        if (i == nsteps - 1) CPA_WAIT(0); else CPA_WAIT(1);
        __syncthreads();
        if (i + 2 < nsteps) ISSUE(i + 2);
        const int buf = i % 3;
        const uint32_t aB = aBase + buf * ABUF;
        const uint32_t bB = bBase + buf * BBUF;
#pragma unroll
        for (int kk = 0; kk < 4; kk++) {
            uint32_t af[4][4];
#pragma unroll
            for (int mi = 0; mi < 4; mi++)
                LDSM4(af[mi][0], af[mi][1], af[mi][2], af[mi][3],
                      aB + mi * (16 * PITCH) + kk * 32);
            uint32_t bfr[4][2];
#pragma unroll
            for (int g = 0; g < 2; g++) {
                uint32_t t0, t1, t2, t3;
                LDSM4(t0, t1, t2, t3, bB + g * (16 * PITCH) + kk * 32);
                bfr[2 * g][0] = t0;     bfr[2 * g][1] = t1;
                bfr[2 * g + 1][0] = t2; bfr[2 * g + 1][1] = t3;
            }
#pragma unroll
            for (int mi = 0; mi < 4; mi++)
#pragma unroll
                for (int ni = 0; ni < 4; ni++)
                    MMA16816(acc[mi][ni], af[mi], bfr[ni]);
        }
    }

    // epilogue
#pragma unroll
    for (int mi = 0; mi < 4; mi++) {
        int r0 = m0 + wm * 64 + mi * 16 + (lane >> 2);
        float* cr0 = C + (size_t)r0 * Cs;
        float* cr1 = C + (size_t)(r0 + 8) * Cs;
        const float* rr0 = res + (size_t)r0 * Cs;
        const float* rr1 = res + (size_t)(r0 + 8) * Cs;
#pragma unroll
        for (int ni = 0; ni < 4; ni++) {
            int c0 = n0 + wn * 32 + ni * 8 + (lane & 3) * 2;
            if (c0 < Nact) {
                float v0 = acc[mi][ni][0] + bias[c0];
                float v2 = acc[mi][ni][2] + bias[c0];
                if (RES) { v0 += rr0[c0]; v2 += rr1[c0]; }
                cr0[c0] = v0; cr1[c0] = v2;
            }
            if (c0 + 1 < Nact) {
                float v1 = acc[mi][ni][1] + bias[c0 + 1];
                float v3 = acc[mi][ni][3] + bias[c0 + 1];
                if (RES) { v1 += rr0[c0 + 1]; v3 += rr1[c0 + 1]; }
                cr0[c0 + 1] = v1; cr1[c0 + 1] = v3;
            }
        }
    }
}

// ---------------- weight conversion (batched over layers via blockIdx.z) ---
__global__ void convB_kernel(const float* __restrict__ W, __nv_bfloat16* __restrict__ dst,
                             int K, int N, int Kpad, size_t wStride, size_t dStride) {
    __shared__ float t[32][33];
    const float* Wl = W + blockIdx.z * wStride;
    __nv_bfloat16* dl = dst + blockIdx.z * dStride;
    int k0 = blockIdx.x * 32, n0 = blockIdx.y * 32;
    int tx = threadIdx.x, ty = threadIdx.y;
#pragma unroll
    for (int i = 0; i < 4; i++) {
        int k = k0 + ty + i * 8, n = n0 + tx;
        t[ty + i * 8][tx] = (k < K && n < N) ? Wl[(size_t)k * N + n] : 0.f;
    }
    __syncthreads();
#pragma unroll
    for (int i = 0; i < 4; i++) {
        int n = n0 + ty + i * 8, k = k0 + tx;
        float v = t[tx][ty + i * 8];
        __nv_bfloat16 hi, lo; split_bf16(v, hi, lo);
        dl[(size_t)n * 2 * Kpad + k] = hi;
        dl[(size_t)n * 2 * Kpad + Kpad + k] = lo;
    }
}

// ---------------- A conversion (layer 0 only) ------------------------------
__global__ void convA_kernel(const float* __restrict__ src, __nv_bfloat16* __restrict__ dst) {
    int m = blockIdx.x;
    const float* s = src + (size_t)m * EMBD;
    __nv_bfloat16* d = dst + (size_t)m * 1024;
    for (int k = threadIdx.x; k < 512; k += 128) {
        __nv_bfloat16 hi, lo; split_bf16(s[k], hi, lo);
        d[k] = hi; d[512 + k] = lo;
    }
}

// ---------------- tokenizer ------------------------------------------------
__global__ void tokenizer_kernel(const float* __restrict__ x,
                                 const float* __restrict__ tok_w,
                                 const float* __restrict__ tok_b,
                                 const float* __restrict__ cat_emb,
                                 float* __restrict__ h) {
    int t = blockIdx.x;
    int b = t / SEQ, s = t % SEQ;
    int e0 = threadIdx.x;
    const float* src;
    float scale = 1.0f;
    const float* brow = nullptr;
    if (s == 0) {
        src = tok_w;
    } else if (s <= NCONT) {
        src = tok_w + (size_t)s * EMBD;
        scale = x[(size_t)b * (NCAT + NCONT) + NCAT + (s - 1)];
        brow = tok_b + (size_t)(s - 1) * EMBD;
    } else {
        int c = s - (NCONT + 1);
        int idx = (int)x[(size_t)b * (NCAT + NCONT) + c] + 100 * c;
        src = cat_emb + (size_t)idx * EMBD;
        brow = tok_b + (size_t)(s - 1) * EMBD;
    }
    float* dst = h + (size_t)t * EMBD;
#pragma unroll
    for (int i = 0; i < 4; i++) {
        int e = e0 + i * 128;
        float v = src[e] * scale;
        if (brow) v += brow[e];
        dst[e] = v;
    }
}

// ---------------- layernorm -> bf16 hi/lo ----------------------------------
__global__ void ln_conv_kernel(const float* __restrict__ in,
                               const float* __restrict__ g,
                               const float* __restrict__ b,
                               __nv_bfloat16* __restrict__ out) {
    int row = blockIdx.x * 8 + threadIdx.y;
    if (row >= NTOK) return;
    const float* p = in + (size_t)row * EMBD;
    int lane = threadIdx.x;
    float v[16];
    float s = 0.f;
#pragma unroll
    for (int i = 0; i < 16; i++) { v[i] = p[lane + 32 * i]; s += v[i]; }
#pragma unroll
    for (int o = 16; o; o >>= 1) s += __shfl_xor_sync(0xffffffffu, s, o);
    float mean = s * (1.0f / EMBD);
    float vs = 0.f;
#pragma unroll
    for (int i = 0; i < 16; i++) { float d = v[i] - mean; vs += d * d; }
#pragma unroll
    for (int o = 16; o; o >>= 1) vs += __shfl_xor_sync(0xffffffffu, vs, o);
    float inv = rsqrtf(vs * (1.0f / EMBD) + 1e-5f);
    __nv_bfloat16* qo = out + (size_t)row * 1024;
#pragma unroll
    for (int i = 0; i < 16; i++) {
        int e = lane + 32 * i;
        float y = (v[i] - mean) * inv * g[e] + b[e];
        __nv_bfloat16 hi, lo; split_bf16(y, hi, lo);
        qo[e] = hi; qo[512 + e] = lo;
    }
}

// ---------------- attention scores -----------------------------------------
__global__ void scores_kernel(const float* __restrict__ qkv,
                              float* __restrict__ scores) {
    extern __shared__ float sm[];
    float* qs = sm;
    float* ks = sm + SEQ * 65;
    int bh = blockIdx.x;
    int b = bh / NHEADS, h = bh % NHEADS;
    const float* basep = qkv + (size_t)b * SEQ * QKVN + h * (3 * HDIM);
    int tid = threadIdx.x;
    for (int i = tid; i < SEQ * HDIM; i += 256) {
        int r = i / HDIM, d = i % HDIM;
        const float* row = basep + (size_t)r * QKVN;
        qs[r * 65 + d] = row[d];
        ks[r * 65 + d] = row[HDIM + d];
    }
    __syncthreads();
    const float scale = 22.62741699796952f;
    float* out = scores + (size_t)bh * SEQ * SEQ;
    for (int idx = tid; idx < SEQ * SEQ; idx += 256) {
        int i = idx / SEQ, j = idx % SEQ;
        const float* qi = qs + i * 65;
        const float* kj = ks + j * 65;
        float acc = 0.f;
#pragma unroll
        for (int d = 0; d < HDIM; d++) acc += qi[d] * kj[d];
        out[idx] = acc * scale;
    }
}

// ---------------- double softmax -------------------------------------------
__global__ void softmax2_kernel(float* __restrict__ scores) {
    int row = blockIdx.x * 8 + threadIdx.y;
    if (row >= NBH * SEQ) return;
    float* p = scores + (size_t)row * SEQ;
    int lane = threadIdx.x;
    float v[5];
    int cnt = 0;
    float mx = -1e30f;
    for (int j = lane; j < SEQ; j += 32) { v[cnt] = p[j]; mx = fmaxf(mx, v[cnt]); cnt++; }
#pragma unroll
    for (int o = 16; o; o >>= 1) mx = fmaxf(mx, __shfl_xor_sync(0xffffffffu, mx, o));
    float s = 0.f;
    for (int c = 0; c < cnt; c++) { v[c] = __expf(v[c] - mx); s += v[c]; }
#pragma unroll
    for (int o = 16; o; o >>= 1) s += __shfl_xor_sync(0xffffffffu, s, o);
    float inv = 1.0f / s;
    mx = -1e30f;
    for (int c = 0; c < cnt; c++) { v[c] *= inv; mx = fmaxf(mx, v[c]); }
#pragma unroll
    for (int o = 16; o; o >>= 1) mx = fmaxf(mx, __shfl_xor_sync(0xffffffffu, mx, o));
    s = 0.f;
    for (int c = 0; c < cnt; c++) { v[c] = __expf(v[c] - mx); s += v[c]; }
#pragma unroll
    for (int o = 16; o; o >>= 1) s += __shfl_xor_sync(0xffffffffu, s, o);
    inv = 1.0f / s;
    cnt = 0;
    for (int j = lane; j < SEQ; j += 32) { p[j] = v[cnt] * inv; cnt++; }
}

// ---------------- attn @ v -> A2 bf16 hi/lo --------------------------------
__global__ void av_conv_kernel(const float* __restrict__ qkv,
                               const float* __restrict__ scores,
                               __nv_bfloat16* __restrict__ a2) {
    extern __shared__ float sm[];
    float* attn = sm;
    float* vs = sm + SEQ * SEQ;
    int bh = blockIdx.x;
    int b = bh / NHEADS, h = bh % NHEADS;
    const float* vbase = qkv + (size_t)b * SEQ * QKVN + h * (3 * HDIM) + 2 * HDIM;
    int tid = threadIdx.y * 64 + threadIdx.x;
    const float* srow = scores + (size_t)bh * SEQ * SEQ;
    for (int i = tid; i < SEQ * SEQ; i += 256) attn[i] = srow[i];
    for (int i = tid; i < SEQ * HDIM; i += 256) {
        int r = i / HDIM, d = i % HDIM;
        vs[r * HDIM + d] = vbase[(size_t)r * QKVN + d];
    }
    __syncthreads();
    int d = threadIdx.x;
    int col = h * HDIM + d;
    for (int i = threadIdx.y; i < SEQ; i += 4) {
        const float* ar = attn + i * SEQ;
        float acc = 0.f;
        for (int j = 0; j < SEQ; j++) acc += ar[j] * vs[j * HDIM + d];
        __nv_bfloat16 hi, lo; split_bf16(acc, hi, lo);
        __nv_bfloat16* dRow = a2 + ((size_t)b * SEQ + i) * 1024;
        dRow[col] = hi; dRow[512 + col] = lo;
    }
}

// ---------------- ReGLU -> A2 bf16 hi/lo (Kpad=704) ------------------------
__global__ void reglu_conv_kernel(const float* __restrict__ u, __nv_bfloat16* __restrict__ a2) {
    int n = blockIdx.x;
    const float* un = u + (size_t)n * HID2;
    __nv_bfloat16* rn = a2 + (size_t)n * 1408;
    for (int j = threadIdx.x; j < KPAD_H; j += 256) {
        float v = (j < NHID) ? un[j] * fmaxf(un[NHID + j], 0.f) : 0.f;
        __nv_bfloat16 hi, lo; split_bf16(v, hi, lo);
        rn[j] = hi; rn[KPAD_H + j] = lo;
    }
}

// ---------------- extract CLS ----------------------------------------------
__global__ void extract_kernel(const float* __restrict__ h, float* __restrict__ out) {
    int b = blockIdx.x;
    int e = threadIdx.x;
    out[(size_t)b * EMBD + e] = h[(size_t)b * SEQ * EMBD + e];
}

// ---------------- host -----------------------------------------------------
extern "C" void kernel_launch(void* const* d_in, const int* in_sizes, int n_in,
                              void* d_out, int out_size) {
    (void)in_sizes; (void)n_in; (void)out_size;
    const float* x       = (const float*)d_in[0];
    const float* tok_w   = (const float*)d_in[1];
    const float* tok_b   = (const float*)d_in[2];
    const float* cat_emb = (const float*)d_in[3];
    const float* Wqkv    = (const float*)d_in[4];
    const float* bqkv    = (const float*)d_in[5];
    const float* Wout    = (const float*)d_in[6];
    const float* bout    = (const float*)d_in[7];
    const float* W0      = (const float*)d_in[8];
    const float* b0      = (const float*)d_in[9];
    const float* W1      = (const float*)d_in[10];
    const float* b1      = (const float*)d_in[11];
    const float* ln0_g   = (const float*)d_in[12];
    const float* ln0_b   = (const float*)d_in[13];
    const float* ln1_g   = (const float*)d_in[14];
    const float* ln1_b   = (const float*)d_in[15];
    float* out = (float*)d_out;

    float *ph, *pqkv, *pscores, *pu;
    __nv_bfloat16 *pa2, *pb2;
    cudaGetSymbolAddress((void**)&ph, g_h);
    cudaGetSymbolAddress((void**)&pqkv, g_qkv);
    cudaGetSymbolAddress((void**)&pscores, g_scores);
    cudaGetSymbolAddress((void**)&pu, g_u);
    cudaGetSymbolAddress((void**)&pa2, g_a2);
    cudaGetSymbolAddress((void**)&pb2, g_b2);

    const int SCORES_SMEM = 2 * SEQ * 65 * 4;
    const int AV_SMEM = (SEQ * SEQ + SEQ * HDIM) * 4;
    cudaFuncSetAttribute(scores_kernel, cudaFuncAttributeMaxDynamicSharedMemorySize, SCORES_SMEM);
    cudaFuncSetAttribute(av_conv_kernel, cudaFuncAttributeMaxDynamicSharedMemorySize, AV_SMEM);
    cudaFuncSetAttribute(gemm_mma, cudaFuncAttributeMaxDynamicSharedMemorySize, GEMM_SMEM);

    // weight conversion, batched over all layers
    {
        __nv_bfloat16* bq  = pb2;
        __nv_bfloat16* bo  = pb2 + B2_QKV_SZ;
        __nv_bfloat16* b0p = pb2 + B2_QKV_SZ + B2_WOUT_SZ;
        __nv_bfloat16* b1p = pb2 + B2_QKV_SZ + B2_WOUT_SZ + B2_W0_SZ;
        convB_kernel<<<dim3(16, 48, NDEPTH), dim3(32, 8)>>>(
            Wqkv, bq, 512, 1536, 512, (size_t)EMBD * QKVN, B2_LAYER);
        convB_kernel<<<dim3(16, 16, NDEPTH), dim3(32, 8)>>>(
            Wout, bo, 512, 512, 512, (size_t)EMBD * EMBD, B2_LAYER);
        convB_kernel<<<dim3(16, 48, NDEPTH), dim3(32, 8)>>>(
            W0, b0p, 512, HID2, 512, (size_t)EMBD * HID2, B2_LAYER);
        convB_kernel<<<dim3(22, 16, NDEPTH), dim3(32, 8)>>>(
            W1, b1p, NHID, 512, KPAD_H, (size_t)NHID * EMBD, B2_LAYER);
    }

    tokenizer_kernel<<<NTOK, 128>>>(x, tok_w, tok_b, cat_emb, ph);

    for (int L = 0; L < NDEPTH; L++) {
        __nv_bfloat16* bq  = pb2 + (size_t)L * B2_LAYER;
        __nv_bfloat16* bo  = bq + B2_QKV_SZ;
        __nv_bfloat16* b0p = bo + B2_WOUT_SZ;
        __nv_bfloat16* b1p = b0p + B2_W0_SZ;

        if (L == 0) {
            convA_kernel<<<NTOK, 128>>>(ph, pa2);
        } else {
            ln_conv_kernel<<<NTOK / 8, dim3(32, 8)>>>(ph, ln0_g + L * EMBD, ln0_b + L * EMBD, pa2);
        }
        gemm_mma<<<dim3(129, 12), 256, GEMM_SMEM>>>(pa2, bq, bqkv + (size_t)L * QKVN,
                                                    ph, pqkv, QKVN, QKVN, KPAD_E, 0);
        scores_kernel<<<NBH, 256, SCORES_SMEM>>>(pqkv, pscores);
        softmax2_kernel<<<NBH * SEQ / 8, dim3(32, 8)>>>(pscores);
        av_conv_kernel<<<NBH, dim3(64, 4), AV_SMEM>>>(pqkv, pscores, pa2);
        gemm_mma<<<dim3(129, 4), 256, GEMM_SMEM>>>(pa2, bo, bout + (size_t)L * EMBD,
                                                   ph, ph, EMBD, EMBD, KPAD_E, 1);
        ln_conv_kernel<<<NTOK / 8, dim3(32, 8)>>>(ph, ln1_g + L * EMBD, ln1_b + L * EMBD, pa2);
        gemm_mma<<<dim3(129, 11), 256, GEMM_SMEM>>>(pa2, b0p, b0 + (size_t)L * HID2,
                                                    ph, pu, HID2, HID2, KPAD_E, 0);
        reglu_conv_kernel<<<NTOK, 256>>>(pu, pa2);
        gemm_mma<<<dim3(129, 4), 256, GEMM_SMEM>>>(pa2, b1p, b1 + (size_t)L * EMBD,
                                                   ph, ph, EMBD, EMBD, KPAD_H, 1);
    }
    extract_kernel<<<BSZ, EMBD>>>(ph, out);
}

// round 7
// speedup vs baseline: 1.7051x; 1.3051x over previous
#include <cuda_runtime.h>
#include <cuda_bf16.h>
#include <cstdint>
#include <math.h>

#define EMBD 512
#define NHEADS 8
#define HDIM 64
#define NDEPTH 6
#define NCONT 100
#define NCAT 28
#define NHID 682
#define BSZ 128
#define SEQ 129
#define NTOK (BSZ*SEQ)      /* 16512 */
#define QKVN (3*EMBD)       /* 1536  */
#define HID2 (2*NHID)       /* 1364  */
#define NBH (BSZ*NHEADS)    /* 1024  */

#define KPAD_E 512
#define KPAD_H 704
#define W0_NPAD 1536

// ---------------- scratch (device globals) ---------------------------------
__device__ float g_h[NTOK*EMBD];
__device__ float g_qkv[NTOK*QKVN];
__device__ float g_u[NTOK*HID2];
__device__ __nv_bfloat16 g_a2[(size_t)NTOK*(2*KPAD_H)];
#define B2_QKV_SZ ((size_t)1536*1024)
#define B2_WOUT_SZ ((size_t)512*1024)
#define B2_W0_SZ ((size_t)W0_NPAD*1024)
#define B2_W1_SZ ((size_t)512*1408)
#define B2_LAYER (B2_QKV_SZ+B2_WOUT_SZ+B2_W0_SZ+B2_W1_SZ)
__device__ __nv_bfloat16 g_b2[B2_LAYER*NDEPTH];

// ---------------- helpers ---------------------------------------------------
__device__ __forceinline__ uint32_t smem_u32(const void* p) {
    uint32_t a;
    asm("{ .reg .u64 t; cvta.to.shared.u64 t, %1; cvt.u32.u64 %0, t; }" : "=r"(a) : "l"(p));
    return a;
}
#define LDSM4(r0, r1, r2, r3, addr) \
    asm volatile("ldmatrix.sync.aligned.m8n8.x4.shared.b16 {%0,%1,%2,%3}, [%4];" \
        : "=r"(r0), "=r"(r1), "=r"(r2), "=r"(r3) : "r"(addr))
#define MMA16816(d, a, b) \
    asm volatile("mma.sync.aligned.m16n8k16.row.col.f32.bf16.bf16.f32 " \
        "{%0,%1,%2,%3},{%4,%5,%6,%7},{%8,%9},{%0,%1,%2,%3};" \
        : "+f"((d)[0]), "+f"((d)[1]), "+f"((d)[2]), "+f"((d)[3]) \
        : "r"((a)[0]), "r"((a)[1]), "r"((a)[2]), "r"((a)[3]), "r"((b)[0]), "r"((b)[1]))
#define CPA16(s, g) \
    asm volatile("cp.async.cg.shared.global [%0], [%1], 16;" :: "r"(s), "l"(g))
#define CPA_COMMIT asm volatile("cp.async.commit_group;" ::: "memory")
#define CPA_WAIT(n) asm volatile("cp.async.wait_group %0;" :: "n"(n) : "memory")

__device__ __forceinline__ void split_bf16(float v, __nv_bfloat16& hi, __nv_bfloat16& lo) {
    hi = __float2bfloat16(v);
    lo = __float2bfloat16(v - __bfloat162float(hi));
}

// ---------------- HMMA GEMM: C[M,Nact] = A2 @ B2^T (3-pass bf16 split) -----
#define PITCH 144
#define ABUF (128*PITCH)
#define BBUF (128*PITCH)
#define BOFF (3*ABUF)
#define GEMM_SMEM (3*(ABUF+BBUF))     /* 110592 B */
__global__ void __launch_bounds__(256, 2)
gemm_mma(const __nv_bfloat16* __restrict__ A2, const __nv_bfloat16* __restrict__ B2,
         const float* __restrict__ bias, const float* __restrict__ res,
         float* __restrict__ C, int Nact, int Cs, int Kpad, int RES) {
    extern __shared__ __nv_bfloat16 dsm[];
    const uint32_t sbase = smem_u32(dsm);
    const int tid = threadIdx.x, lane = tid & 31, wid = tid >> 5;
    const int wm = wid & 1, wn = wid >> 1;
    const int m0 = blockIdx.x * 128, n0 = blockIdx.y * 128;
    const int sA2 = 2 * Kpad;
    const int KC = Kpad >> 6;
    const int nsteps = 3 * KC;

    float acc[4][4][4];
#pragma unroll
    for (int a = 0; a < 4; a++)
#pragma unroll
        for (int b = 0; b < 4; b++)
#pragma unroll
            for (int c = 0; c < 4; c++) acc[a][b][c] = 0.f;

    const int rT = tid >> 3, cT = tid & 7;
    const uint32_t sA0 = sbase + rT * PITCH + cT * 16;
    const uint32_t sB0 = sbase + BOFF + rT * PITCH + cT * 16;
    const __nv_bfloat16* gA0 = A2 + (size_t)(m0 + rT) * sA2 + cT * 8;
    const __nv_bfloat16* gB0 = B2 + (size_t)(n0 + rT) * sA2 + cT * 8;

#define ISSUE(i) do { \
    int pass = ((i) >= 2 * KC) ? 2 : (((i) >= KC) ? 1 : 0); \
    int kc = (i) - pass * KC; \
    int aO = ((pass == 2) ? Kpad : 0) + kc * 64; \
    int bO = ((pass == 1) ? Kpad : 0) + kc * 64; \
    int bufi = (i) % 3; \
    uint32_t sa = sA0 + bufi * ABUF; \
    uint32_t sb = sB0 + bufi * BBUF; \
    CPA16(sa,             gA0 + aO); \
    CPA16(sa + 32*PITCH,  gA0 + aO + (size_t)32 * sA2); \
    CPA16(sa + 64*PITCH,  gA0 + aO + (size_t)64 * sA2); \
    CPA16(sa + 96*PITCH,  gA0 + aO + (size_t)96 * sA2); \
    CPA16(sb,             gB0 + bO); \
    CPA16(sb + 32*PITCH,  gB0 + bO + (size_t)32 * sA2); \
    CPA16(sb + 64*PITCH,  gB0 + bO + (size_t)64 * sA2); \
    CPA16(sb + 96*PITCH,  gB0 + bO + (size_t)96 * sA2); \
    CPA_COMMIT; \
} while (0)

    const int q = lane >> 3, rr = lane & 7;
    const uint32_t aBase = sbase +
        (uint32_t)((wm * 64 + (q & 1) * 8 + rr) * PITCH + (q >> 1) * 16);
    const uint32_t bBase = sbase + BOFF +
        (uint32_t)((wn * 32 + (q >> 1) * 8 + rr) * PITCH + (q & 1) * 16);

    ISSUE(0);
    ISSUE(1);

    for (int i = 0; i < nsteps; i++) {
        if (i == nsteps - 1) CPA_WAIT(0); else CPA_WAIT(1);
        __syncthreads();
        if (i + 2 < nsteps) ISSUE(i + 2);
        const int buf = i % 3;
        const uint32_t aB = aBase + buf * ABUF;
        const uint32_t bB = bBase + buf * BBUF;
#pragma unroll
        for (int kk = 0; kk < 4; kk++) {
            uint32_t af[4][4];
#pragma unroll
            for (int mi = 0; mi < 4; mi++)
                LDSM4(af[mi][0], af[mi][1], af[mi][2], af[mi][3],
                      aB + mi * (16 * PITCH) + kk * 32);
            uint32_t bfr[4][2];
#pragma unroll
            for (int g = 0; g < 2; g++) {
                uint32_t t0, t1, t2, t3;
                LDSM4(t0, t1, t2, t3, bB + g * (16 * PITCH) + kk * 32);
                bfr[2 * g][0] = t0;     bfr[2 * g][1] = t1;
                bfr[2 * g + 1][0] = t2; bfr[2 * g + 1][1] = t3;
            }
#pragma unroll
            for (int mi = 0; mi < 4; mi++)
#pragma unroll
                for (int ni = 0; ni < 4; ni++)
                    MMA16816(acc[mi][ni], af[mi], bfr[ni]);
        }
    }

#pragma unroll
    for (int mi = 0; mi < 4; mi++) {
        int r0 = m0 + wm * 64 + mi * 16 + (lane >> 2);
        float* cr0 = C + (size_t)r0 * Cs;
        float* cr1 = C + (size_t)(r0 + 8) * Cs;
        const float* rr0 = res + (size_t)r0 * Cs;
        const float* rr1 = res + (size_t)(r0 + 8) * Cs;
#pragma unroll
        for (int ni = 0; ni < 4; ni++) {
            int c0 = n0 + wn * 32 + ni * 8 + (lane & 3) * 2;
            if (c0 < Nact) {
                float v0 = acc[mi][ni][0] + bias[c0];
                float v2 = acc[mi][ni][2] + bias[c0];
                if (RES) { v0 += rr0[c0]; v2 += rr1[c0]; }
                cr0[c0] = v0; cr1[c0] = v2;
            }
            if (c0 + 1 < Nact) {
                float v1 = acc[mi][ni][1] + bias[c0 + 1];
                float v3 = acc[mi][ni][3] + bias[c0 + 1];
                if (RES) { v1 += rr0[c0 + 1]; v3 += rr1[c0 + 1]; }
                cr0[c0 + 1] = v1; cr1[c0 + 1] = v3;
            }
        }
    }
}

// ---------------- fused attention: S=qk^T, double softmax, O=Sv -> a2 ------
// smem floats: qT[64][132] | kT[64][132] | v[129][68] | S[16][132]
#define ATT_KT (64*132)
#define ATT_V  (2*64*132)                 /* 16896 */
#define ATT_S  (2*64*132 + 129*68)        /* 16896 + 8772 = 25668 */
#define ATT_SMEM ((ATT_S + 16*132)*4)     /* (25668+2112)*4 = 111120 B */
__global__ void __launch_bounds__(256, 2)
attn_fused(const float* __restrict__ qkv, __nv_bfloat16* __restrict__ a2) {
    extern __shared__ float sf[];
    float* qT = sf;                // [64][132]
    float* kT = sf + ATT_KT;       // [64][132]
    float* vv = sf + ATT_V;        // [129][68]
    float* S  = sf + ATT_S;        // [16][132]
    const int bh = blockIdx.x;
    const int b = bh >> 3, h = bh & 7;
    const float* base = qkv + (size_t)b * SEQ * QKVN + h * (3 * HDIM);
    const int t = threadIdx.x, lane = t & 31, w = t >> 5;
    const float scale = 22.62741699796952f;   // sqrt(512)

    // phase 1: load q,k (transposed) and v
    for (int idx = t; idx < SEQ * HDIM; idx += 256) {
        int j = idx >> 6, d = idx & 63;
        const float* row = base + (size_t)j * QKVN;
        qT[d * 132 + j] = row[d];
        kT[d * 132 + j] = row[HDIM + d];
        vv[j * 68 + d]  = row[2 * HDIM + d];
    }
    __syncthreads();

    for (int blk = 0; blk < 8; blk++) {
        const int r0 = blk * 16;
        // ---- phase 2: S[16][129] = q[r0..r0+15] @ k^T * scale ----
        {
            // warp w: rows r0 + 2w + {0,1}; lane: cols lane*4..+3
            float a0x = 0.f, a0y = 0.f, a0z = 0.f, a0w = 0.f;
            float a1x = 0.f, a1y = 0.f, a1z = 0.f, a1w = 0.f;
#pragma unroll 4
            for (int d = 0; d < 64; d++) {
                float2 qf = *(const float2*)&qT[d * 132 + r0 + w * 2];
                float4 kf = *(const float4*)&kT[d * 132 + lane * 4];
                a0x += qf.x * kf.x; a0y += qf.x * kf.y;
                a0z += qf.x * kf.z; a0w += qf.x * kf.w;
                a1x += qf.y * kf.x; a1y += qf.y * kf.y;
                a1z += qf.y * kf.z; a1w += qf.y * kf.w;
            }
            float* s0 = S + (w * 2) * 132 + lane * 4;
            s0[0] = a0x * scale; s0[1] = a0y * scale;
            s0[2] = a0z * scale; s0[3] = a0w * scale;
            float* s1 = s0 + 132;
            s1[0] = a1x * scale; s1[1] = a1y * scale;
            s1[2] = a1z * scale; s1[3] = a1w * scale;
            if (t < 16) {   // col 128 edge
                float a = 0.f;
                for (int d = 0; d < 64; d++)
                    a += qT[d * 132 + r0 + t] * kT[d * 132 + 128];
                S[t * 132 + 128] = a * scale;
            }
        }
        __syncthreads();
        // ---- phase 3: double softmax (warp w: rows 2w, 2w+1) ----
#pragma unroll
        for (int rr = 0; rr < 2; rr++) {
            float* p = S + (w * 2 + rr) * 132;
            float v[5];
            int cnt = 0;
            float mx = -1e30f;
            for (int j = lane; j < SEQ; j += 32) { v[cnt] = p[j]; mx = fmaxf(mx, v[cnt]); cnt++; }
#pragma unroll
            for (int o = 16; o; o >>= 1) mx = fmaxf(mx, __shfl_xor_sync(0xffffffffu, mx, o));
            float s = 0.f;
            for (int c = 0; c < cnt; c++) { v[c] = __expf(v[c] - mx); s += v[c]; }
#pragma unroll
            for (int o = 16; o; o >>= 1) s += __shfl_xor_sync(0xffffffffu, s, o);
            float inv = 1.0f / s;
            mx = -1e30f;
            for (int c = 0; c < cnt; c++) { v[c] *= inv; mx = fmaxf(mx, v[c]); }
#pragma unroll
            for (int o = 16; o; o >>= 1) mx = fmaxf(mx, __shfl_xor_sync(0xffffffffu, mx, o));
            s = 0.f;
            for (int c = 0; c < cnt; c++) { v[c] = __expf(v[c] - mx); s += v[c]; }
#pragma unroll
            for (int o = 16; o; o >>= 1) s += __shfl_xor_sync(0xffffffffu, s, o);
            inv = 1.0f / s;
            cnt = 0;
            for (int j = lane; j < SEQ; j += 32) { p[j] = v[cnt] * inv; cnt++; }
        }
        __syncthreads();
        // ---- phase 4: O[16][64] = S @ v -> split-bf16 a2 ----
        if (t < 128) {
            int rt = t >> 4, ct = t & 15;   // rows r0+rt*2+{0,1}, cols ct*4..+3
            const float* s0 = S + (rt * 2) * 132;
            const float* s1 = s0 + 132;
            float a00 = 0.f, a01 = 0.f, a02 = 0.f, a03 = 0.f;
            float a10 = 0.f, a11 = 0.f, a12 = 0.f, a13 = 0.f;
            for (int j = 0; j < SEQ; j++) {
                float4 vf = *(const float4*)&vv[j * 68 + ct * 4];
                float x0 = s0[j], x1 = s1[j];
                a00 += x0 * vf.x; a01 += x0 * vf.y; a02 += x0 * vf.z; a03 += x0 * vf.w;
                a10 += x1 * vf.x; a11 += x1 * vf.y; a12 += x1 * vf.z; a13 += x1 * vf.w;
            }
            int m = b * SEQ + r0 + rt * 2;
            int col = h * HDIM + ct * 4;
            __nv_bfloat16* d0 = a2 + (size_t)m * 1024;
            __nv_bfloat16* d1 = d0 + 1024;
            __nv_bfloat16 hi, lo;
            split_bf16(a00, hi, lo); d0[col]     = hi; d0[512 + col]     = lo;
            split_bf16(a01, hi, lo); d0[col + 1] = hi; d0[512 + col + 1] = lo;
            split_bf16(a02, hi, lo); d0[col + 2] = hi; d0[512 + col + 2] = lo;
            split_bf16(a03, hi, lo); d0[col + 3] = hi; d0[512 + col + 3] = lo;
            split_bf16(a10, hi, lo); d1[col]     = hi; d1[512 + col]     = lo;
            split_bf16(a11, hi, lo); d1[col + 1] = hi; d1[512 + col + 1] = lo;
            split_bf16(a12, hi, lo); d1[col + 2] = hi; d1[512 + col + 2] = lo;
            split_bf16(a13, hi, lo); d1[col + 3] = hi; d1[512 + col + 3] = lo;
        }
        __syncthreads();
    }

    // ---- edge row 128 ----
    for (int j = t; j < SEQ; j += 256) {
        float a = 0.f;
        for (int d = 0; d < 64; d++)
            a += qT[d * 132 + 128] * kT[d * 132 + j];
        S[j] = a * scale;
    }
    __syncthreads();
    if (w == 0) {
        float* p = S;
        float v[5];
        int cnt = 0;
        float mx = -1e30f;
        for (int j = lane; j < SEQ; j += 32) { v[cnt] = p[j]; mx = fmaxf(mx, v[cnt]); cnt++; }
#pragma unroll
        for (int o = 16; o; o >>= 1) mx = fmaxf(mx, __shfl_xor_sync(0xffffffffu, mx, o));
        float s = 0.f;
        for (int c = 0; c < cnt; c++) { v[c] = __expf(v[c] - mx); s += v[c]; }
#pragma unroll
        for (int o = 16; o; o >>= 1) s += __shfl_xor_sync(0xffffffffu, s, o);
        float inv = 1.0f / s;
        mx = -1e30f;
        for (int c = 0; c < cnt; c++) { v[c] *= inv; mx = fmaxf(mx, v[c]); }
#pragma unroll
        for (int o = 16; o; o >>= 1) mx = fmaxf(mx, __shfl_xor_sync(0xffffffffu, mx, o));
        s = 0.f;
        for (int c = 0; c < cnt; c++) { v[c] = __expf(v[c] - mx); s += v[c]; }
#pragma unroll
        for (int o = 16; o; o >>= 1) s += __shfl_xor_sync(0xffffffffu, s, o);
        inv = 1.0f / s;
        cnt = 0;
        for (int j = lane; j < SEQ; j += 32) { p[j] = v[cnt] * inv; cnt++; }
    }
    __syncthreads();
    if (t < 64) {
        float a = 0.f;
        for (int j = 0; j < SEQ; j++) a += S[j] * vv[j * 68 + t];
        int m = b * SEQ + 128;
        int col = h * HDIM + t;
        __nv_bfloat16* d0 = a2 + (size_t)m * 1024;
        __nv_bfloat16 hi, lo;
        split_bf16(a, hi, lo); d0[col] = hi; d0[512 + col] = lo;
    }
}

// ---------------- weight conversion (batched over layers via blockIdx.z) ---
__global__ void convB_kernel(const float* __restrict__ W, __nv_bfloat16* __restrict__ dst,
                             int K, int N, int Kpad, size_t wStride, size_t dStride) {
    __shared__ float t[32][33];
    const float* Wl = W + blockIdx.z * wStride;
    __nv_bfloat16* dl = dst + blockIdx.z * dStride;
    int k0 = blockIdx.x * 32, n0 = blockIdx.y * 32;
    int tx = threadIdx.x, ty = threadIdx.y;
#pragma unroll
    for (int i = 0; i < 4; i++) {
        int k = k0 + ty + i * 8, n = n0 + tx;
        t[ty + i * 8][tx] = (k < K && n < N) ? Wl[(size_t)k * N + n] : 0.f;
    }
    __syncthreads();
#pragma unroll
    for (int i = 0; i < 4; i++) {
        int n = n0 + ty + i * 8, k = k0 + tx;
        float v = t[tx][ty + i * 8];
        __nv_bfloat16 hi, lo; split_bf16(v, hi, lo);
        dl[(size_t)n * 2 * Kpad + k] = hi;
        dl[(size_t)n * 2 * Kpad + Kpad + k] = lo;
    }
}

// ---------------- A conversion (layer 0 only) ------------------------------
__global__ void convA_kernel(const float* __restrict__ src, __nv_bfloat16* __restrict__ dst) {
    int m = blockIdx.x;
    const float* s = src + (size_t)m * EMBD;
    __nv_bfloat16* d = dst + (size_t)m * 1024;
    for (int k = threadIdx.x; k < 512; k += 128) {
        __nv_bfloat16 hi, lo; split_bf16(s[k], hi, lo);
        d[k] = hi; d[512 + k] = lo;
    }
}

// ---------------- tokenizer ------------------------------------------------
__global__ void tokenizer_kernel(const float* __restrict__ x,
                                 const float* __restrict__ tok_w,
                                 const float* __restrict__ tok_b,
                                 const float* __restrict__ cat_emb,
                                 float* __restrict__ h) {
    int t = blockIdx.x;
    int b = t / SEQ, s = t % SEQ;
    int e0 = threadIdx.x;
    const float* src;
    float scale = 1.0f;
    const float* brow = nullptr;
    if (s == 0) {
        src = tok_w;
    } else if (s <= NCONT) {
        src = tok_w + (size_t)s * EMBD;
        scale = x[(size_t)b * (NCAT + NCONT) + NCAT + (s - 1)];
        brow = tok_b + (size_t)(s - 1) * EMBD;
    } else {
        int c = s - (NCONT + 1);
        int idx = (int)x[(size_t)b * (NCAT + NCONT) + c] + 100 * c;
        src = cat_emb + (size_t)idx * EMBD;
        brow = tok_b + (size_t)(s - 1) * EMBD;
    }
    float* dst = h + (size_t)t * EMBD;
#pragma unroll
    for (int i = 0; i < 4; i++) {
        int e = e0 + i * 128;
        float v = src[e] * scale;
        if (brow) v += brow[e];
        dst[e] = v;
    }
}

// ---------------- layernorm -> bf16 hi/lo ----------------------------------
__global__ void ln_conv_kernel(const float* __restrict__ in,
                               const float* __restrict__ g,
                               const float* __restrict__ b,
                               __nv_bfloat16* __restrict__ out) {
    int row = blockIdx.x * 8 + threadIdx.y;
    if (row >= NTOK) return;
    const float* p = in + (size_t)row * EMBD;
    int lane = threadIdx.x;
    float v[16];
    float s = 0.f;
#pragma unroll
    for (int i = 0; i < 16; i++) { v[i] = p[lane + 32 * i]; s += v[i]; }
#pragma unroll
    for (int o = 16; o; o >>= 1) s += __shfl_xor_sync(0xffffffffu, s, o);
    float mean = s * (1.0f / EMBD);
    float vs = 0.f;
#pragma unroll
    for (int i = 0; i < 16; i++) { float d = v[i] - mean; vs += d * d; }
#pragma unroll
    for (int o = 16; o; o >>= 1) vs += __shfl_xor_sync(0xffffffffu, vs, o);
    float inv = rsqrtf(vs * (1.0f / EMBD) + 1e-5f);
    __nv_bfloat16* qo = out + (size_t)row * 1024;
#pragma unroll
    for (int i = 0; i < 16; i++) {
        int e = lane + 32 * i;
        float y = (v[i] - mean) * inv * g[e] + b[e];
        __nv_bfloat16 hi, lo; split_bf16(y, hi, lo);
        qo[e] = hi; qo[512 + e] = lo;
    }
}

// ---------------- ReGLU -> A2 bf16 hi/lo (Kpad=704) ------------------------
__global__ void reglu_conv_kernel(const float* __restrict__ u, __nv_bfloat16* __restrict__ a2) {
    int n = blockIdx.x;
    const float* un = u + (size_t)n * HID2;
    __nv_bfloat16* rn = a2 + (size_t)n * 1408;
    for (int j = threadIdx.x; j < KPAD_H; j += 256) {
        float v = (j < NHID) ? un[j] * fmaxf(un[NHID + j], 0.f) : 0.f;
        __nv_bfloat16 hi, lo; split_bf16(v, hi, lo);
        rn[j] = hi; rn[KPAD_H + j] = lo;
    }
}

// ---------------- extract CLS ----------------------------------------------
__global__ void extract_kernel(const float* __restrict__ h, float* __restrict__ out) {
    int b = blockIdx.x;
    int e = threadIdx.x;
    out[(size_t)b * EMBD + e] = h[(size_t)b * SEQ * EMBD + e];
}

// ---------------- host -----------------------------------------------------
extern "C" void kernel_launch(void* const* d_in, const int* in_sizes, int n_in,
                              void* d_out, int out_size) {
    (void)in_sizes; (void)n_in; (void)out_size;
    const float* x       = (const float*)d_in[0];
    const float* tok_w   = (const float*)d_in[1];
    const float* tok_b   = (const float*)d_in[2];
    const float* cat_emb = (const float*)d_in[3];
    const float* Wqkv    = (const float*)d_in[4];
    const float* bqkv    = (const float*)d_in[5];
    const float* Wout    = (const float*)d_in[6];
    const float* bout    = (const float*)d_in[7];
    const float* W0      = (const float*)d_in[8];
    const float* b0      = (const float*)d_in[9];
    const float* W1      = (const float*)d_in[10];
    const float* b1      = (const float*)d_in[11];
    const float* ln0_g   = (const float*)d_in[12];
    const float* ln0_b   = (const float*)d_in[13];
    const float* ln1_g   = (const float*)d_in[14];
    const float* ln1_b   = (const float*)d_in[15];
    float* out = (float*)d_out;

    float *ph, *pqkv, *pu;
    __nv_bfloat16 *pa2, *pb2;
    cudaGetSymbolAddress((void**)&ph, g_h);
    cudaGetSymbolAddress((void**)&pqkv, g_qkv);
    cudaGetSymbolAddress((void**)&pu, g_u);
    cudaGetSymbolAddress((void**)&pa2, g_a2);
    cudaGetSymbolAddress((void**)&pb2, g_b2);

    cudaFuncSetAttribute(gemm_mma, cudaFuncAttributeMaxDynamicSharedMemorySize, GEMM_SMEM);
    cudaFuncSetAttribute(attn_fused, cudaFuncAttributeMaxDynamicSharedMemorySize, ATT_SMEM);

    // weight conversion, batched over all layers
    {
        __nv_bfloat16* bq  = pb2;
        __nv_bfloat16* bo  = pb2 + B2_QKV_SZ;
        __nv_bfloat16* b0p = pb2 + B2_QKV_SZ + B2_WOUT_SZ;
        __nv_bfloat16* b1p = pb2 + B2_QKV_SZ + B2_WOUT_SZ + B2_W0_SZ;
        convB_kernel<<<dim3(16, 48, NDEPTH), dim3(32, 8)>>>(
            Wqkv, bq, 512, 1536, 512, (size_t)EMBD * QKVN, B2_LAYER);
        convB_kernel<<<dim3(16, 16, NDEPTH), dim3(32, 8)>>>(
            Wout, bo, 512, 512, 512, (size_t)EMBD * EMBD, B2_LAYER);
        convB_kernel<<<dim3(16, 48, NDEPTH), dim3(32, 8)>>>(
            W0, b0p, 512, HID2, 512, (size_t)EMBD * HID2, B2_LAYER);
        convB_kernel<<<dim3(22, 16, NDEPTH), dim3(32, 8)>>>(
            W1, b1p, NHID, 512, KPAD_H, (size_t)NHID * EMBD, B2_LAYER);
    }

    tokenizer_kernel<<<NTOK, 128>>>(x, tok_w, tok_b, cat_emb, ph);

    for (int L = 0; L < NDEPTH; L++) {
        __nv_bfloat16* bq  = pb2 + (size_t)L * B2_LAYER;
        __nv_bfloat16* bo  = bq + B2_QKV_SZ;
        __nv_bfloat16* b0p = bo + B2_WOUT_SZ;
        __nv_bfloat16* b1p = b0p + B2_W0_SZ;

        if (L == 0) {
            convA_kernel<<<NTOK, 128>>>(ph, pa2);
        } else {
            ln_conv_kernel<<<NTOK / 8, dim3(32, 8)>>>(ph, ln0_g + L * EMBD, ln0_b + L * EMBD, pa2);
        }
        gemm_mma<<<dim3(129, 12), 256, GEMM_SMEM>>>(pa2, bq, bqkv + (size_t)L * QKVN,
                                                    ph, pqkv, QKVN, QKVN, KPAD_E, 0);
        attn_fused<<<NBH, 256, ATT_SMEM>>>(pqkv, pa2);
        gemm_mma<<<dim3(129, 4), 256, GEMM_SMEM>>>(pa2, bo, bout + (size_t)L * EMBD,
                                                   ph, ph, EMBD, EMBD, KPAD_E, 1);
        ln_conv_kernel<<<NTOK / 8, dim3(32, 8)>>>(ph, ln1_g + L * EMBD, ln1_b + L * EMBD, pa2);
        gemm_mma<<<dim3(129, 11), 256, GEMM_SMEM>>>(pa2, b0p, b0 + (size_t)L * HID2,
                                                    ph, pu, HID2, HID2, KPAD_E, 0);
        reglu_conv_kernel<<<NTOK, 256>>>(pu, pa2);
        gemm_mma<<<dim3(129, 4), 256, GEMM_SMEM>>>(pa2, b1p, b1 + (size_t)L * EMBD,
                                                   ph, ph, EMBD, EMBD, KPAD_H, 1);
    }
    extract_kernel<<<BSZ, EMBD>>>(ph, out);
}